// round 7
// baseline (speedup 1.0000x reference)
#include <cuda_runtime.h>
#include <math.h>
#include <stdint.h>

// Problem constants
#define BB    4
#define NQ    2048
#define NKV   4096
#define QDIM  512
#define KVDIM 128
#define NH    8
#define HD    64
#define INNER 512
// attention scale folded with log2(e): 0.125 * 1.4426950408889634
#define Q_PRESCALE 0.18033688011112042f

// ---------------------------------------------------------------------------
// Scratch.  g_Vp holds V TRANSPOSED: [b][h][d][key]
// ---------------------------------------------------------------------------
__device__ float g_Qp[BB * NQ  * INNER];
__device__ float g_Kp[BB * NKV * INNER];
__device__ float g_Vp[BB * NKV * INNER];
__device__ float g_AO[BB * NQ  * INNER];

// ---------------------------------------------------------------------------
// Helpers
// ---------------------------------------------------------------------------
__device__ __forceinline__ uint32_t smem_u32(const void* p) {
    uint32_t a;
    asm("{ .reg .u64 t; cvta.to.shared.u64 t, %1; cvt.u32.u64 %0, t; }"
        : "=r"(a) : "l"(p));
    return a;
}
__device__ __forceinline__ void cp16(uint32_t dst, const void* src) {
    asm volatile("cp.async.cg.shared.global [%0], [%1], 16;\n"
                 :: "r"(dst), "l"(src));
}
#define CP_COMMIT() asm volatile("cp.async.commit_group;\n")
#define CP_WAIT1()  asm volatile("cp.async.wait_group 1;\n")
#define CP_WAIT0()  asm volatile("cp.async.wait_group 0;\n")

__device__ __forceinline__ uint32_t f2tf32(float x) {
    uint32_t r;
    asm("cvt.rna.tf32.f32 %0, %1;" : "=r"(r) : "f"(x));
    return r;
}
__device__ __forceinline__ uint32_t u2tf32(uint32_t u) {
    uint32_t r;
    asm("cvt.rna.tf32.f32 %0, %1;" : "=r"(r) : "f"(__uint_as_float(u)));
    return r;
}
__device__ __forceinline__ float ex2(float x) {
    float r;
    asm("ex2.approx.f32 %0, %1;" : "=f"(r) : "f"(x));
    return r;
}
__device__ __forceinline__ void mma_tf32(float d[4], const uint32_t a[4],
                                         const uint32_t b[2], const float c[4]) {
    asm volatile(
        "mma.sync.aligned.m16n8k8.row.col.f32.tf32.tf32.f32 "
        "{%0,%1,%2,%3}, {%4,%5,%6,%7}, {%8,%9}, {%10,%11,%12,%13};\n"
        : "=f"(d[0]), "=f"(d[1]), "=f"(d[2]), "=f"(d[3])
        : "r"(a[0]), "r"(a[1]), "r"(a[2]), "r"(a[3]),
          "r"(b[0]), "r"(b[1]),
          "f"(c[0]), "f"(c[1]), "f"(c[2]), "f"(c[3]));
}
// ldmatrix x4: four 8x8 b16 matrices; on fp32 data, mat(left16B) gives
// thread(g,t) element [g][t], mat(right16B) gives [g][t+4].
__device__ __forceinline__ void ldsm4(uint32_t& r0, uint32_t& r1,
                                      uint32_t& r2, uint32_t& r3, uint32_t addr) {
    asm volatile("ldmatrix.sync.aligned.m8n8.x4.shared.b16 {%0,%1,%2,%3}, [%4];\n"
                 : "=r"(r0), "=r"(r1), "=r"(r2), "=r"(r3) : "r"(addr));
}

// ---------------------------------------------------------------------------
// TF32 NT GEMM: C[M,N] = scale*(A[M,K] @ W[N,K]^T) (+ bias)
// ROUND_OUT: RNA-round outputs to tf32.  WRITE_VT: scatter into [b][h][d][key].
// ---------------------------------------------------------------------------
#define GBM 128
#define GBN 64
#define GBK 32
#define GSTR 36
#define GEMM_SMEM ((2*GBM*GSTR + 2*GBN*GSTR)*4)

template <bool HAS_BIAS, bool ROUND_OUT, bool WRITE_VT>
__global__ __launch_bounds__(256) void gemm_tf32_kernel(
    const float* __restrict__ A, const float* __restrict__ W,
    const float* __restrict__ bias, float* __restrict__ C,
    int M, int N, int K, float scale)
{
    extern __shared__ uint32_t gsm[];
    uint32_t* sA = gsm;
    uint32_t* sW = gsm + 2*GBM*GSTR;
    const uint32_t sA_u = smem_u32(sA);
    const uint32_t sW_u = smem_u32(sW);

    const int tid = threadIdx.x;
    const int lane = tid & 31, w = tid >> 5;
    const int g = lane >> 2, t = lane & 3;
    const int bm = blockIdx.y * GBM, bn = blockIdx.x * GBN;
    const int NIT = K / GBK;

    float acc[8][4];
#pragma unroll
    for (int nb = 0; nb < 8; nb++)
#pragma unroll
        for (int j = 0; j < 4; j++) acc[nb][j] = 0.f;

    {
#pragma unroll
        for (int i = 0; i < 4; i++) {
            int idx = tid + i*256, row = idx >> 3, c = idx & 7;
            cp16(sA_u + (row*GSTR + c*4)*4, A + (size_t)(bm + row)*K + c*4);
        }
#pragma unroll
        for (int i = 0; i < 2; i++) {
            int idx = tid + i*256, row = idx >> 3, c = idx & 7;
            cp16(sW_u + (row*GSTR + c*4)*4, W + (size_t)(bn + row)*K + c*4);
        }
        CP_COMMIT();
    }

    for (int it = 0; it < NIT; it++) {
        const int buf = it & 1;
        if (it + 1 < NIT) {
            const int k0 = (it + 1) * GBK, nb_ = (buf ^ 1);
#pragma unroll
            for (int i = 0; i < 4; i++) {
                int idx = tid + i*256, row = idx >> 3, c = idx & 7;
                cp16(sA_u + (nb_*GBM*GSTR + row*GSTR + c*4)*4,
                     A + (size_t)(bm + row)*K + k0 + c*4);
            }
#pragma unroll
            for (int i = 0; i < 2; i++) {
                int idx = tid + i*256, row = idx >> 3, c = idx & 7;
                cp16(sW_u + (nb_*GBN*GSTR + row*GSTR + c*4)*4,
                     W + (size_t)(bn + row)*K + k0 + c*4);
            }
            CP_COMMIT();
            CP_WAIT1();
        } else {
            CP_WAIT0();
        }
        __syncthreads();

        const uint32_t* tA = sA + buf*GBM*GSTR;
        const uint32_t* tW = sW + buf*GBN*GSTR;
#pragma unroll
        for (int ks = 0; ks < 4; ks++) {
            const int col = ks*8 + t;
            uint32_t a[4];
            a[0] = u2tf32(tA[(w*16 + g    )*GSTR + col]);
            a[1] = u2tf32(tA[(w*16 + g + 8)*GSTR + col]);
            a[2] = u2tf32(tA[(w*16 + g    )*GSTR + col + 4]);
            a[3] = u2tf32(tA[(w*16 + g + 8)*GSTR + col + 4]);
#pragma unroll
            for (int nb = 0; nb < 8; nb++) {
                uint32_t bfr[2];
                bfr[0] = u2tf32(tW[(nb*8 + g)*GSTR + col]);
                bfr[1] = u2tf32(tW[(nb*8 + g)*GSTR + col + 4]);
                mma_tf32(acc[nb], a, bfr, acc[nb]);
            }
        }
        __syncthreads();
    }

    const int r0 = bm + w*16 + g, r1 = r0 + 8;
#pragma unroll
    for (int nb = 0; nb < 8; nb++) {
        const int col = bn + nb*8 + 2*t;
        float v00 = acc[nb][0]*scale, v01 = acc[nb][1]*scale;
        float v10 = acc[nb][2]*scale, v11 = acc[nb][3]*scale;
        if (HAS_BIAS) {
            float b0 = bias[col], b1 = bias[col + 1];
            v00 += b0; v01 += b1; v10 += b0; v11 += b1;
        }
        if (ROUND_OUT) {
            v00 = __uint_as_float(f2tf32(v00)); v01 = __uint_as_float(f2tf32(v01));
            v10 = __uint_as_float(f2tf32(v10)); v11 = __uint_as_float(f2tf32(v11));
        }
        if (WRITE_VT) {
            // rows are (b*NKV + key); cols are h*HD + d.  Write [b][h][d][key].
            int b_ = r0 >> 12;                     // NKV = 4096
            int key0 = r0 & (NKV - 1), key1 = r1 & (NKV - 1);
            size_t base0 = ((size_t)(b_*NH + (col >> 6))*HD + (col & 63)) * NKV;
            size_t base1 = base0 + NKV;            // col+1 stays within the head
            C[base0 + key0] = v00; C[base1 + key0] = v01;
            C[base0 + key1] = v10; C[base1 + key1] = v11;
        } else {
            *(float2*)&C[(size_t)r0*N + col] = make_float2(v00, v01);
            *(float2*)&C[(size_t)r1*N + col] = make_float2(v10, v11);
        }
    }
}

// ---------------------------------------------------------------------------
// Flash-attention core.  All operands pre-rounded tf32 (raw-bit feed);
// fragment loads via ldmatrix.x4; V consumed from transposed layout.
// Block = (128 q rows, head, batch), 256 threads = 8 warps x 16 q rows.
// Strides 68 words (== 4 mod 32 banks -> LDSM rows conflict-free).
// ---------------------------------------------------------------------------
#define BQ   128
#define KT   64
#define KSTR 68
#define VSTR 68
#define NITA (NKV / KT)
#define ATTN_SMEM ((2*KT*KSTR + 2*KT*VSTR + BQ*KSTR)*4)

__global__ __launch_bounds__(256) void attn_mma_kernel()
{
    extern __shared__ uint32_t sm[];
    uint32_t* sK  = sm;                     // 2 x 64 x 68   [key][d]
    uint32_t* sVt = sm + 2*KT*KSTR;         // 2 x 64 x 68   [d][key]
    uint32_t* sP  = sVt + 2*KT*VSTR;        // 128 x 68 (Q staging, then P)
    const uint32_t sK_u  = smem_u32(sK);
    const uint32_t sVt_u = smem_u32(sVt);
    const uint32_t sP_u  = smem_u32(sP);

    const int qt = blockIdx.x, h = blockIdx.y, b = blockIdx.z;
    const int tid = threadIdx.x, lane = tid & 31, w = tid >> 5;
    const int g = lane >> 2, t = lane & 3;

    const float* Qb  = g_Qp + (size_t)(b*NQ + qt*BQ)*INNER + h*HD;
    const float* Kb  = g_Kp + (size_t)b*NKV*INNER + h*HD;
    const float* Vtb = g_Vp + ((size_t)(b*NH + h)*HD)*NKV;   // [d][key]

    // per-thread LDSM row addresses (word offsets)
    // K/V: lanes 0-7: mat(nb0,left); 8-15: (nb0,right); 16-23: (nb0+1,left); 24-31: right
    const int kvbase = ((lane >> 4)*8 + (lane & 7))*KSTR + ((lane >> 3) & 1)*4;
    // P: lanes 0-15 rows 0-15 (left), 16-31 rows 0-15 (right)
    const int pbase  = (lane & 15)*KSTR + (lane >> 4)*4;

    // ---- stage Q via cp.async (group 0) ----
#pragma unroll
    for (int i = 0; i < 8; i++) {
        int idx = tid + i*256, row = idx >> 4, c = idx & 15;
        cp16(sP_u + (row*KSTR + c*4)*4, Qb + (size_t)row*INNER + c*4);
    }
    CP_COMMIT();

    // ---- first K/V^T tile (group 1) ----
#pragma unroll
    for (int i = 0; i < 4; i++) {
        int idx = tid + i*256, row = idx >> 4, c = idx & 15;
        cp16(sK_u  + (row*KSTR + c*4)*4, Kb  + (size_t)row*INNER + c*4);
        cp16(sVt_u + (row*VSTR + c*4)*4, Vtb + (size_t)row*NKV   + c*4);
    }
    CP_COMMIT();

    CP_WAIT1();
    __syncthreads();

    // ---- lift Q fragments (each warp reads only its own 16 rows) ----
    uint32_t qa[8][4];
#pragma unroll
    for (int ks = 0; ks < 8; ks++) {
        const int col = ks*8 + t;
        qa[ks][0] = sP[(w*16 + g    )*KSTR + col];
        qa[ks][1] = sP[(w*16 + g + 8)*KSTR + col];
        qa[ks][2] = sP[(w*16 + g    )*KSTR + col + 4];
        qa[ks][3] = sP[(w*16 + g + 8)*KSTR + col + 4];
    }

    float m0 = -INFINITY, m1 = -INFINITY, l0 = 0.f, l1 = 0.f;
    float o[8][4];
#pragma unroll
    for (int db = 0; db < 8; db++)
#pragma unroll
        for (int j = 0; j < 4; j++) o[db][j] = 0.f;

    uint32_t* sPw = sP + (w*16)*KSTR;
    const uint32_t sPw_u = sP_u + (w*16)*KSTR*4;

    for (int it = 0; it < NITA; it++) {
        const int buf = it & 1;
        if (it + 1 < NITA) {
            const int nbuf = buf ^ 1;
#pragma unroll
            for (int i = 0; i < 4; i++) {
                int idx = tid + i*256, row = idx >> 4, c = idx & 15;
                cp16(sK_u  + (nbuf*KT*KSTR + row*KSTR + c*4)*4,
                     Kb  + (size_t)((it + 1)*KT + row)*INNER + c*4);
                cp16(sVt_u + (nbuf*KT*VSTR + row*VSTR + c*4)*4,
                     Vtb + (size_t)row*NKV + (it + 1)*KT + c*4);
            }
            CP_COMMIT();
            CP_WAIT1();
        } else {
            CP_WAIT0();
        }
        __syncthreads();

        const uint32_t tK_u  = sK_u  + buf*KT*KSTR*4;
        const uint32_t tVt_u = sVt_u + buf*KT*VSTR*4;

        // ---- S = Q K^T : B-fragments via LDSM (2 key-blocks per op) ----
        float s[8][4];
#pragma unroll
        for (int nb = 0; nb < 8; nb++)
#pragma unroll
            for (int j = 0; j < 4; j++) s[nb][j] = 0.f;

#pragma unroll
        for (int ks = 0; ks < 8; ks++) {
#pragma unroll
            for (int p = 0; p < 4; p++) {
                uint32_t b0, b1, b2, b3;
                ldsm4(b0, b1, b2, b3, tK_u + (p*16*KSTR + kvbase + ks*8)*4);
                uint32_t bl[2] = {b0, b1}, bh[2] = {b2, b3};
                mma_tf32(s[2*p    ], qa[ks], bl, s[2*p    ]);
                mma_tf32(s[2*p + 1], qa[ks], bh, s[2*p + 1]);
            }
        }

        // ---- online softmax (exp2 domain) ----
        float rm0 = -INFINITY, rm1 = -INFINITY;
#pragma unroll
        for (int nb = 0; nb < 8; nb++) {
            rm0 = fmaxf(rm0, fmaxf(s[nb][0], s[nb][1]));
            rm1 = fmaxf(rm1, fmaxf(s[nb][2], s[nb][3]));
        }
        rm0 = fmaxf(rm0, __shfl_xor_sync(0xffffffffu, rm0, 1));
        rm0 = fmaxf(rm0, __shfl_xor_sync(0xffffffffu, rm0, 2));
        rm1 = fmaxf(rm1, __shfl_xor_sync(0xffffffffu, rm1, 1));
        rm1 = fmaxf(rm1, __shfl_xor_sync(0xffffffffu, rm1, 2));

        float mn0 = fmaxf(m0, rm0), mn1 = fmaxf(m1, rm1);
        float corr0 = ex2(m0 - mn0), corr1 = ex2(m1 - mn1);
        m0 = mn0; m1 = mn1;

        float rs0 = 0.f, rs1 = 0.f;
#pragma unroll
        for (int nb = 0; nb < 8; nb++) {
            s[nb][0] = ex2(s[nb][0] - m0);
            s[nb][1] = ex2(s[nb][1] - m0);
            s[nb][2] = ex2(s[nb][2] - m1);
            s[nb][3] = ex2(s[nb][3] - m1);
            rs0 += s[nb][0] + s[nb][1];
            rs1 += s[nb][2] + s[nb][3];
        }
        rs0 += __shfl_xor_sync(0xffffffffu, rs0, 1);
        rs0 += __shfl_xor_sync(0xffffffffu, rs0, 2);
        rs1 += __shfl_xor_sync(0xffffffffu, rs1, 1);
        rs1 += __shfl_xor_sync(0xffffffffu, rs1, 2);
        l0 = l0 * corr0 + rs0;
        l1 = l1 * corr1 + rs1;

#pragma unroll
        for (int db = 0; db < 8; db++) {
            o[db][0] *= corr0; o[db][1] *= corr0;
            o[db][2] *= corr1; o[db][3] *= corr1;
        }

        // ---- P -> smem (RNA tf32 once, STS.64), re-read via LDSM ----
#pragma unroll
        for (int nb = 0; nb < 8; nb++) {
            *(uint2*)&sPw[(g    )*KSTR + nb*8 + 2*t] =
                make_uint2(f2tf32(s[nb][0]), f2tf32(s[nb][1]));
            *(uint2*)&sPw[(g + 8)*KSTR + nb*8 + 2*t] =
                make_uint2(f2tf32(s[nb][2]), f2tf32(s[nb][3]));
        }
        __syncwarp();

        // ---- O += P V : A via LDSM on P, B via LDSM on V^T ----
#pragma unroll
        for (int ks = 0; ks < 8; ks++) {
            uint32_t pa[4];
            ldsm4(pa[0], pa[1], pa[2], pa[3], sPw_u + (pbase + ks*8)*4);
#pragma unroll
            for (int p = 0; p < 4; p++) {
                uint32_t b0, b1, b2, b3;
                ldsm4(b0, b1, b2, b3, tVt_u + (p*16*VSTR + kvbase + ks*8)*4);
                uint32_t bl[2] = {b0, b1}, bh[2] = {b2, b3};
                mma_tf32(o[2*p    ], pa, bl, o[2*p    ]);
                mma_tf32(o[2*p + 1], pa, bh, o[2*p + 1]);
            }
        }
        __syncthreads();
    }

    // ---- epilogue ----
    const float inv0 = 1.f / l0, inv1 = 1.f / l1;
    const int q0 = qt*BQ + w*16 + g, q1 = q0 + 8;
#pragma unroll
    for (int db = 0; db < 8; db++) {
        float2 r0 = make_float2(o[db][0]*inv0, o[db][1]*inv0);
        float2 r1 = make_float2(o[db][2]*inv1, o[db][3]*inv1);
        *(float2*)&g_AO[(size_t)(b*NQ + q0)*INNER + h*HD + db*8 + 2*t] = r0;
        *(float2*)&g_AO[(size_t)(b*NQ + q1)*INNER + h*HD + db*8 + 2*t] = r1;
    }
}

// ---------------------------------------------------------------------------
// Launch
// ---------------------------------------------------------------------------
extern "C" void kernel_launch(void* const* d_in, const int* in_sizes, int n_in,
                              void* d_out, int out_size)
{
    const float* q   = (const float*)d_in[0];
    const float* kv  = (const float*)d_in[1];
    const float* w_q = (const float*)d_in[2];
    const float* w_k = (const float*)d_in[3];
    const float* w_v = (const float*)d_in[4];
    const float* w_o = (const float*)d_in[5];
    const float* b_o = (const float*)d_in[6];
    float* out = (float*)d_out;

    float *Qp, *Kp, *Vp, *AO;
    cudaGetSymbolAddress((void**)&Qp, g_Qp);
    cudaGetSymbolAddress((void**)&Kp, g_Kp);
    cudaGetSymbolAddress((void**)&Vp, g_Vp);
    cudaGetSymbolAddress((void**)&AO, g_AO);

    const int MQ = BB * NQ;    // 8192
    const int MK = BB * NKV;   // 16384

    cudaFuncSetAttribute(gemm_tf32_kernel<false, true, false>,
                         cudaFuncAttributeMaxDynamicSharedMemorySize, GEMM_SMEM);
    cudaFuncSetAttribute(gemm_tf32_kernel<false, true, true>,
                         cudaFuncAttributeMaxDynamicSharedMemorySize, GEMM_SMEM);
    cudaFuncSetAttribute(gemm_tf32_kernel<true, false, false>,
                         cudaFuncAttributeMaxDynamicSharedMemorySize, GEMM_SMEM);
    cudaFuncSetAttribute(attn_mma_kernel,
                         cudaFuncAttributeMaxDynamicSharedMemorySize, ATTN_SMEM);

    // Q projection: pre-scaled by 0.125*log2(e), tf32-rounded
    gemm_tf32_kernel<false, true, false><<<dim3(INNER/GBN, MQ/GBM), 256, GEMM_SMEM>>>(
        q, w_q, nullptr, Qp, MQ, INNER, QDIM, Q_PRESCALE);
    // K projection: tf32-rounded
    gemm_tf32_kernel<false, true, false><<<dim3(INNER/GBN, MK/GBM), 256, GEMM_SMEM>>>(
        kv, w_k, nullptr, Kp, MK, INNER, KVDIM, 1.0f);
    // V projection: tf32-rounded, written TRANSPOSED [b][h][d][key]
    gemm_tf32_kernel<false, true, true><<<dim3(INNER/GBN, MK/GBM), 256, GEMM_SMEM>>>(
        kv, w_v, nullptr, Vp, MK, INNER, KVDIM, 1.0f);

    attn_mma_kernel<<<dim3(NQ/BQ, NH, BB), 256, ATTN_SMEM>>>();

    // Output projection: fp32 epilogue + bias
    gemm_tf32_kernel<true, false, false><<<dim3(QDIM/GBN, MQ/GBM), 256, GEMM_SMEM>>>(
        AO, w_o, b_o, out, MQ, QDIM, INNER, 1.0f);
}

// round 9
// speedup vs baseline: 1.0778x; 1.0778x over previous
#include <cuda_runtime.h>
#include <math.h>
#include <stdint.h>

// Problem constants
#define BB    4
#define NQ    2048
#define NKV   4096
#define QDIM  512
#define KVDIM 128
#define NH    8
#define HD    64
#define INNER 512
// attention scale folded with log2(e): 0.125 * 1.4426950408889634
#define Q_PRESCALE 0.18033688011112042f

// ---------------------------------------------------------------------------
// Scratch.  g_Vp holds V TRANSPOSED: [b][h][d][key]
// ---------------------------------------------------------------------------
__device__ float g_Qp[BB * NQ  * INNER];
__device__ float g_Kp[BB * NKV * INNER];
__device__ float g_Vp[BB * NKV * INNER];
__device__ float g_AO[BB * NQ  * INNER];
// tf32-pre-rounded copies of inputs (GEMMs feed raw bits, no in-loop cvt)
__device__ float g_Rq [BB * NQ  * QDIM];
__device__ float g_Rkv[BB * NKV * KVDIM];
__device__ float g_Rwq[INNER * QDIM];
__device__ float g_Rwk[INNER * KVDIM];
__device__ float g_Rwv[INNER * KVDIM];
__device__ float g_Rwo[QDIM * INNER];

// ---------------------------------------------------------------------------
// Helpers
// ---------------------------------------------------------------------------
__device__ __forceinline__ uint32_t smem_u32(const void* p) {
    uint32_t a;
    asm("{ .reg .u64 t; cvta.to.shared.u64 t, %1; cvt.u32.u64 %0, t; }"
        : "=r"(a) : "l"(p));
    return a;
}
__device__ __forceinline__ void cp16(uint32_t dst, const void* src) {
    asm volatile("cp.async.cg.shared.global [%0], [%1], 16;\n"
                 :: "r"(dst), "l"(src));
}
#define CP_COMMIT() asm volatile("cp.async.commit_group;\n")
#define CP_WAIT1()  asm volatile("cp.async.wait_group 1;\n")
#define CP_WAIT0()  asm volatile("cp.async.wait_group 0;\n")

__device__ __forceinline__ uint32_t f2tf32(float x) {
    uint32_t r;
    asm("cvt.rna.tf32.f32 %0, %1;" : "=r"(r) : "f"(x));
    return r;
}
__device__ __forceinline__ float ex2(float x) {
    float r;
    asm("ex2.approx.f32 %0, %1;" : "=f"(r) : "f"(x));
    return r;
}
__device__ __forceinline__ void mma_tf32(float d[4], const uint32_t a[4],
                                         const uint32_t b[2], const float c[4]) {
    asm volatile(
        "mma.sync.aligned.m16n8k8.row.col.f32.tf32.tf32.f32 "
        "{%0,%1,%2,%3}, {%4,%5,%6,%7}, {%8,%9}, {%10,%11,%12,%13};\n"
        : "=f"(d[0]), "=f"(d[1]), "=f"(d[2]), "=f"(d[3])
        : "r"(a[0]), "r"(a[1]), "r"(a[2]), "r"(a[3]),
          "r"(b[0]), "r"(b[1]),
          "f"(c[0]), "f"(c[1]), "f"(c[2]), "f"(c[3]));
}
__device__ __forceinline__ void ldsm4(uint32_t& r0, uint32_t& r1,
                                      uint32_t& r2, uint32_t& r3, uint32_t addr) {
    asm volatile("ldmatrix.sync.aligned.m8n8.x4.shared.b16 {%0,%1,%2,%3}, [%4];\n"
                 : "=r"(r0), "=r"(r1), "=r"(r2), "=r"(r3) : "r"(addr));
}

// ---------------------------------------------------------------------------
// Elementwise RNA tf32 rounding (producer-side; consumers feed raw bits)
// ---------------------------------------------------------------------------
__global__ __launch_bounds__(256) void round_tf32_kernel(
    const float* __restrict__ in, float* __restrict__ out, int n4)
{
    int i = blockIdx.x * 256 + threadIdx.x;
    if (i < n4) {
        float4 v = ((const float4*)in)[i];
        uint4 u = make_uint4(f2tf32(v.x), f2tf32(v.y), f2tf32(v.z), f2tf32(v.w));
        ((uint4*)out)[i] = u;
    }
}

// ---------------------------------------------------------------------------
// TF32 NT GEMM (operands pre-rounded): C = scale*(A @ W^T) (+ bias)
// ---------------------------------------------------------------------------
#define GBM 128
#define GBN 64
#define GBK 32
#define GSTR 36
#define GEMM_SMEM ((2*GBM*GSTR + 2*GBN*GSTR)*4)

template <bool HAS_BIAS, bool ROUND_OUT, bool WRITE_VT>
__global__ __launch_bounds__(256) void gemm_tf32_kernel(
    const float* __restrict__ A, const float* __restrict__ W,
    const float* __restrict__ bias, float* __restrict__ C,
    int M, int N, int K, float scale)
{
    extern __shared__ uint32_t gsm[];
    uint32_t* sA = gsm;
    uint32_t* sW = gsm + 2*GBM*GSTR;
    const uint32_t sA_u = smem_u32(sA);
    const uint32_t sW_u = smem_u32(sW);

    const int tid = threadIdx.x;
    const int lane = tid & 31, w = tid >> 5;
    const int g = lane >> 2, t = lane & 3;
    const int bm = blockIdx.y * GBM, bn = blockIdx.x * GBN;
    const int NIT = K / GBK;

    float acc[8][4];
#pragma unroll
    for (int nb = 0; nb < 8; nb++)
#pragma unroll
        for (int j = 0; j < 4; j++) acc[nb][j] = 0.f;

    {
#pragma unroll
        for (int i = 0; i < 4; i++) {
            int idx = tid + i*256, row = idx >> 3, c = idx & 7;
            cp16(sA_u + (row*GSTR + c*4)*4, A + (size_t)(bm + row)*K + c*4);
        }
#pragma unroll
        for (int i = 0; i < 2; i++) {
            int idx = tid + i*256, row = idx >> 3, c = idx & 7;
            cp16(sW_u + (row*GSTR + c*4)*4, W + (size_t)(bn + row)*K + c*4);
        }
        CP_COMMIT();
    }

    for (int it = 0; it < NIT; it++) {
        const int buf = it & 1;
        if (it + 1 < NIT) {
            const int k0 = (it + 1) * GBK, nb_ = (buf ^ 1);
#pragma unroll
            for (int i = 0; i < 4; i++) {
                int idx = tid + i*256, row = idx >> 3, c = idx & 7;
                cp16(sA_u + (nb_*GBM*GSTR + row*GSTR + c*4)*4,
                     A + (size_t)(bm + row)*K + k0 + c*4);
            }
#pragma unroll
            for (int i = 0; i < 2; i++) {
                int idx = tid + i*256, row = idx >> 3, c = idx & 7;
                cp16(sW_u + (nb_*GBN*GSTR + row*GSTR + c*4)*4,
                     W + (size_t)(bn + row)*K + k0 + c*4);
            }
            CP_COMMIT();
            CP_WAIT1();
        } else {
            CP_WAIT0();
        }
        __syncthreads();

        const uint32_t* tA = sA + buf*GBM*GSTR;
        const uint32_t* tW = sW + buf*GBN*GSTR;
#pragma unroll
        for (int ks = 0; ks < 4; ks++) {
            const int col = ks*8 + t;
            uint32_t a[4];
            a[0] = tA[(w*16 + g    )*GSTR + col];
            a[1] = tA[(w*16 + g + 8)*GSTR + col];
            a[2] = tA[(w*16 + g    )*GSTR + col + 4];
            a[3] = tA[(w*16 + g + 8)*GSTR + col + 4];
#pragma unroll
            for (int nb = 0; nb < 8; nb++) {
                uint32_t bfr[2];
                bfr[0] = tW[(nb*8 + g)*GSTR + col];
                bfr[1] = tW[(nb*8 + g)*GSTR + col + 4];
                mma_tf32(acc[nb], a, bfr, acc[nb]);
            }
        }
        __syncthreads();
    }

    const int r0 = bm + w*16 + g, r1 = r0 + 8;
#pragma unroll
    for (int nb = 0; nb < 8; nb++) {
        const int col = bn + nb*8 + 2*t;
        float v00 = acc[nb][0]*scale, v01 = acc[nb][1]*scale;
        float v10 = acc[nb][2]*scale, v11 = acc[nb][3]*scale;
        if (HAS_BIAS) {
            float b0 = bias[col], b1 = bias[col + 1];
            v00 += b0; v01 += b1; v10 += b0; v11 += b1;
        }
        if (ROUND_OUT) {
            v00 = __uint_as_float(f2tf32(v00)); v01 = __uint_as_float(f2tf32(v01));
            v10 = __uint_as_float(f2tf32(v10)); v11 = __uint_as_float(f2tf32(v11));
        }
        if (WRITE_VT) {
            int b_ = r0 >> 12;
            int key0 = r0 & (NKV - 1), key1 = r1 & (NKV - 1);
            size_t base0 = ((size_t)(b_*NH + (col >> 6))*HD + (col & 63)) * NKV;
            size_t base1 = base0 + NKV;
            C[base0 + key0] = v00; C[base1 + key0] = v01;
            C[base0 + key1] = v10; C[base1 + key1] = v11;
        } else {
            *(float2*)&C[(size_t)r0*N + col] = make_float2(v00, v01);
            *(float2*)&C[(size_t)r1*N + col] = make_float2(v10, v11);
        }
    }
}

// ---------------------------------------------------------------------------
// Flash-attention core.  4 warps x 32 q-rows (2 m16 blocks per warp) ->
// each K/V fragment feeds 2 MMAs, halving smem bytes per FLOP.
// 128 threads, BQ=128; smem ~102KB -> 2 CTAs/SM.
// ---------------------------------------------------------------------------
#define BQ   128
#define KT   64
#define KSTR 68
#define VSTR 68
#define NITA (NKV / KT)
#define ATTN_SMEM ((2*KT*KSTR + 2*KT*VSTR + BQ*KSTR)*4)

__global__ __launch_bounds__(128, 2) void attn_mma_kernel()
{
    extern __shared__ uint32_t sm[];
    uint32_t* sK  = sm;                     // 2 x 64 x 68   [key][d]
    uint32_t* sVt = sm + 2*KT*KSTR;         // 2 x 64 x 68   [d][key]
    uint32_t* sP  = sVt + 2*KT*VSTR;        // 128 x 68 (Q staging, then P)
    const uint32_t sK_u  = smem_u32(sK);
    const uint32_t sVt_u = smem_u32(sVt);
    const uint32_t sP_u  = smem_u32(sP);

    const int qt = blockIdx.x, h = blockIdx.y, b = blockIdx.z;
    const int tid = threadIdx.x, lane = tid & 31, w = tid >> 5;
    const int g = lane >> 2, t = lane & 3;

    const float* Qb  = g_Qp + (size_t)(b*NQ + qt*BQ)*INNER + h*HD;
    const float* Kb  = g_Kp + (size_t)b*NKV*INNER + h*HD;
    const float* Vtb = g_Vp + ((size_t)(b*NH + h)*HD)*NKV;

    const int kvbase = ((lane >> 4)*8 + (lane & 7))*KSTR + ((lane >> 3) & 1)*4;
    const int pbase  = (lane & 15)*KSTR + (lane >> 4)*4;

    // ---- stage Q via cp.async (group 0): 128 rows x 16 float4, 128 thr ----
#pragma unroll
    for (int i = 0; i < 16; i++) {
        int idx = tid + i*128, row = idx >> 4, c = idx & 15;
        cp16(sP_u + (row*KSTR + c*4)*4, Qb + (size_t)row*INNER + c*4);
    }
    CP_COMMIT();

    // ---- first K/V^T tile (group 1) ----
#pragma unroll
    for (int i = 0; i < 8; i++) {
        int idx = tid + i*128, row = idx >> 4, c = idx & 15;
        cp16(sK_u  + (row*KSTR + c*4)*4, Kb  + (size_t)row*INNER + c*4);
        cp16(sVt_u + (row*VSTR + c*4)*4, Vtb + (size_t)row*NKV   + c*4);
    }
    CP_COMMIT();

    CP_WAIT1();
    __syncthreads();

    // ---- lift Q fragments for both row-blocks ----
    uint32_t qa[2][8][4];
#pragma unroll
    for (int r = 0; r < 2; r++)
#pragma unroll
        for (int ks = 0; ks < 8; ks++) {
            const int col = ks*8 + t;
            const int row = w*32 + r*16;
            qa[r][ks][0] = sP[(row + g    )*KSTR + col];
            qa[r][ks][1] = sP[(row + g + 8)*KSTR + col];
            qa[r][ks][2] = sP[(row + g    )*KSTR + col + 4];
            qa[r][ks][3] = sP[(row + g + 8)*KSTR + col + 4];
        }

    float m0[2], m1[2], l0[2], l1[2];
#pragma unroll
    for (int r = 0; r < 2; r++) { m0[r] = m1[r] = -INFINITY; l0[r] = l1[r] = 0.f; }
    float o[2][8][4];
#pragma unroll
    for (int r = 0; r < 2; r++)
#pragma unroll
        for (int db = 0; db < 8; db++)
#pragma unroll
            for (int j = 0; j < 4; j++) o[r][db][j] = 0.f;

    uint32_t* sPw = sP + (w*32)*KSTR;
    const uint32_t sPw_u = sP_u + (w*32)*KSTR*4;

    for (int it = 0; it < NITA; it++) {
        const int buf = it & 1;
        if (it + 1 < NITA) {
            const int nbuf = buf ^ 1;
#pragma unroll
            for (int i = 0; i < 8; i++) {
                int idx = tid + i*128, row = idx >> 4, c = idx & 15;
                cp16(sK_u  + (nbuf*KT*KSTR + row*KSTR + c*4)*4,
                     Kb  + (size_t)((it + 1)*KT + row)*INNER + c*4);
                cp16(sVt_u + (nbuf*KT*VSTR + row*VSTR + c*4)*4,
                     Vtb + (size_t)row*NKV + (it + 1)*KT + c*4);
            }
            CP_COMMIT();
            CP_WAIT1();
        } else {
            CP_WAIT0();
        }
        __syncthreads();

        const uint32_t tK_u  = sK_u  + buf*KT*KSTR*4;
        const uint32_t tVt_u = sVt_u + buf*KT*VSTR*4;

        // ---- S = Q K^T : each K fragment feeds BOTH row-blocks ----
        float s[2][8][4];
#pragma unroll
        for (int r = 0; r < 2; r++)
#pragma unroll
            for (int nb = 0; nb < 8; nb++)
#pragma unroll
                for (int j = 0; j < 4; j++) s[r][nb][j] = 0.f;

#pragma unroll
        for (int ks = 0; ks < 8; ks++) {
#pragma unroll
            for (int p = 0; p < 4; p++) {
                uint32_t b0, b1, b2, b3;
                ldsm4(b0, b1, b2, b3, tK_u + (p*16*KSTR + kvbase + ks*8)*4);
                uint32_t bl[2] = {b0, b1}, bh[2] = {b2, b3};
                mma_tf32(s[0][2*p    ], qa[0][ks], bl, s[0][2*p    ]);
                mma_tf32(s[0][2*p + 1], qa[0][ks], bh, s[0][2*p + 1]);
                mma_tf32(s[1][2*p    ], qa[1][ks], bl, s[1][2*p    ]);
                mma_tf32(s[1][2*p + 1], qa[1][ks], bh, s[1][2*p + 1]);
            }
        }

        // ---- online softmax (exp2 domain), per row-block ----
#pragma unroll
        for (int r = 0; r < 2; r++) {
            float rm0 = -INFINITY, rm1 = -INFINITY;
#pragma unroll
            for (int nb = 0; nb < 8; nb++) {
                rm0 = fmaxf(rm0, fmaxf(s[r][nb][0], s[r][nb][1]));
                rm1 = fmaxf(rm1, fmaxf(s[r][nb][2], s[r][nb][3]));
            }
            rm0 = fmaxf(rm0, __shfl_xor_sync(0xffffffffu, rm0, 1));
            rm0 = fmaxf(rm0, __shfl_xor_sync(0xffffffffu, rm0, 2));
            rm1 = fmaxf(rm1, __shfl_xor_sync(0xffffffffu, rm1, 1));
            rm1 = fmaxf(rm1, __shfl_xor_sync(0xffffffffu, rm1, 2));

            float mn0 = fmaxf(m0[r], rm0), mn1 = fmaxf(m1[r], rm1);
            float corr0 = ex2(m0[r] - mn0), corr1 = ex2(m1[r] - mn1);
            m0[r] = mn0; m1[r] = mn1;

            float rs0 = 0.f, rs1 = 0.f;
#pragma unroll
            for (int nb = 0; nb < 8; nb++) {
                s[r][nb][0] = ex2(s[r][nb][0] - mn0);
                s[r][nb][1] = ex2(s[r][nb][1] - mn0);
                s[r][nb][2] = ex2(s[r][nb][2] - mn1);
                s[r][nb][3] = ex2(s[r][nb][3] - mn1);
                rs0 += s[r][nb][0] + s[r][nb][1];
                rs1 += s[r][nb][2] + s[r][nb][3];
            }
            rs0 += __shfl_xor_sync(0xffffffffu, rs0, 1);
            rs0 += __shfl_xor_sync(0xffffffffu, rs0, 2);
            rs1 += __shfl_xor_sync(0xffffffffu, rs1, 1);
            rs1 += __shfl_xor_sync(0xffffffffu, rs1, 2);
            l0[r] = l0[r] * corr0 + rs0;
            l1[r] = l1[r] * corr1 + rs1;

#pragma unroll
            for (int db = 0; db < 8; db++) {
                o[r][db][0] *= corr0; o[r][db][1] *= corr0;
                o[r][db][2] *= corr1; o[r][db][3] *= corr1;
            }

            // P -> smem (RNA tf32, STS.64)
#pragma unroll
            for (int nb = 0; nb < 8; nb++) {
                *(uint2*)&sPw[(r*16 + g    )*KSTR + nb*8 + 2*t] =
                    make_uint2(f2tf32(s[r][nb][0]), f2tf32(s[r][nb][1]));
                *(uint2*)&sPw[(r*16 + g + 8)*KSTR + nb*8 + 2*t] =
                    make_uint2(f2tf32(s[r][nb][2]), f2tf32(s[r][nb][3]));
            }
        }
        __syncwarp();

        // ---- O += P V : each V fragment feeds BOTH row-blocks ----
#pragma unroll
        for (int ks = 0; ks < 8; ks++) {
            uint32_t pa0[4], pa1[4];
            ldsm4(pa0[0], pa0[1], pa0[2], pa0[3], sPw_u + (pbase + ks*8)*4);
            ldsm4(pa1[0], pa1[1], pa1[2], pa1[3], sPw_u + (16*KSTR + pbase + ks*8)*4);
#pragma unroll
            for (int p = 0; p < 4; p++) {
                uint32_t b0, b1, b2, b3;
                ldsm4(b0, b1, b2, b3, tVt_u + (p*16*VSTR + kvbase + ks*8)*4);
                uint32_t bl[2] = {b0, b1}, bh[2] = {b2, b3};
                mma_tf32(o[0][2*p    ], pa0, bl, o[0][2*p    ]);
                mma_tf32(o[0][2*p + 1], pa0, bh, o[0][2*p + 1]);
                mma_tf32(o[1][2*p    ], pa1, bl, o[1][2*p    ]);
                mma_tf32(o[1][2*p + 1], pa1, bh, o[1][2*p + 1]);
            }
        }
        __syncthreads();
    }

    // ---- epilogue: normalize, tf32-round (O-proj feeds raw bits) ----
#pragma unroll
    for (int r = 0; r < 2; r++) {
        const float inv0 = 1.f / l0[r], inv1 = 1.f / l1[r];
        const int q0 = qt*BQ + w*32 + r*16 + g, q1 = q0 + 8;
#pragma unroll
        for (int db = 0; db < 8; db++) {
            uint2 r0v = make_uint2(f2tf32(o[r][db][0]*inv0), f2tf32(o[r][db][1]*inv0));
            uint2 r1v = make_uint2(f2tf32(o[r][db][2]*inv1), f2tf32(o[r][db][3]*inv1));
            *(uint2*)&g_AO[(size_t)(b*NQ + q0)*INNER + h*HD + db*8 + 2*t] = r0v;
            *(uint2*)&g_AO[(size_t)(b*NQ + q1)*INNER + h*HD + db*8 + 2*t] = r1v;
        }
    }
}

// ---------------------------------------------------------------------------
// Launch
// ---------------------------------------------------------------------------
extern "C" void kernel_launch(void* const* d_in, const int* in_sizes, int n_in,
                              void* d_out, int out_size)
{
    const float* q   = (const float*)d_in[0];
    const float* kv  = (const float*)d_in[1];
    const float* w_q = (const float*)d_in[2];
    const float* w_k = (const float*)d_in[3];
    const float* w_v = (const float*)d_in[4];
    const float* w_o = (const float*)d_in[5];
    const float* b_o = (const float*)d_in[6];
    float* out = (float*)d_out;

    float *Qp, *Kp, *Vp, *AO, *Rq, *Rkv, *Rwq, *Rwk, *Rwv, *Rwo;
    cudaGetSymbolAddress((void**)&Qp,  g_Qp);
    cudaGetSymbolAddress((void**)&Kp,  g_Kp);
    cudaGetSymbolAddress((void**)&Vp,  g_Vp);
    cudaGetSymbolAddress((void**)&AO,  g_AO);
    cudaGetSymbolAddress((void**)&Rq,  g_Rq);
    cudaGetSymbolAddress((void**)&Rkv, g_Rkv);
    cudaGetSymbolAddress((void**)&Rwq, g_Rwq);
    cudaGetSymbolAddress((void**)&Rwk, g_Rwk);
    cudaGetSymbolAddress((void**)&Rwv, g_Rwv);
    cudaGetSymbolAddress((void**)&Rwo, g_Rwo);

    const int MQ = BB * NQ;    // 8192
    const int MK = BB * NKV;   // 16384

    cudaFuncSetAttribute(gemm_tf32_kernel<false, true, false>,
                         cudaFuncAttributeMaxDynamicSharedMemorySize, GEMM_SMEM);
    cudaFuncSetAttribute(gemm_tf32_kernel<false, true, true>,
                         cudaFuncAttributeMaxDynamicSharedMemorySize, GEMM_SMEM);
    cudaFuncSetAttribute(gemm_tf32_kernel<true, false, false>,
                         cudaFuncAttributeMaxDynamicSharedMemorySize, GEMM_SMEM);
    cudaFuncSetAttribute(attn_mma_kernel,
                         cudaFuncAttributeMaxDynamicSharedMemorySize, ATTN_SMEM);

    // ---- pre-round all GEMM inputs to tf32 (RNA, once) ----
    {
        int n;
        n = MQ*QDIM/4;      round_tf32_kernel<<<(n+255)/256, 256>>>(q,   Rq,  n);
        n = MK*KVDIM/4;     round_tf32_kernel<<<(n+255)/256, 256>>>(kv,  Rkv, n);
        n = INNER*QDIM/4;   round_tf32_kernel<<<(n+255)/256, 256>>>(w_q, Rwq, n);
        n = INNER*KVDIM/4;  round_tf32_kernel<<<(n+255)/256, 256>>>(w_k, Rwk, n);
        n = INNER*KVDIM/4;  round_tf32_kernel<<<(n+255)/256, 256>>>(w_v, Rwv, n);
        n = QDIM*INNER/4;   round_tf32_kernel<<<(n+255)/256, 256>>>(w_o, Rwo, n);
    }

    // Q projection: pre-scaled by 0.125*log2(e), tf32-rounded output
    gemm_tf32_kernel<false, true, false><<<dim3(INNER/GBN, MQ/GBM), 256, GEMM_SMEM>>>(
        Rq, Rwq, nullptr, Qp, MQ, INNER, QDIM, Q_PRESCALE);
    // K projection: tf32-rounded output
    gemm_tf32_kernel<false, true, false><<<dim3(INNER/GBN, MK/GBM), 256, GEMM_SMEM>>>(
        Rkv, Rwk, nullptr, Kp, MK, INNER, KVDIM, 1.0f);
    // V projection: tf32-rounded, written TRANSPOSED [b][h][d][key]
    gemm_tf32_kernel<false, true, true><<<dim3(INNER/GBN, MK/GBM), 256, GEMM_SMEM>>>(
        Rkv, Rwv, nullptr, Vp, MK, INNER, KVDIM, 1.0f);

    attn_mma_kernel<<<dim3(NQ/BQ, NH, BB), 128, ATTN_SMEM>>>();

    // Output projection: fp32 epilogue + bias (AO already tf32-rounded)
    gemm_tf32_kernel<true, false, false><<<dim3(QDIM/GBN, MQ/GBM), 256, GEMM_SMEM>>>(
        AO, Rwo, b_o, out, MQ, QDIM, INNER, 1.0f);
}

// round 10
// speedup vs baseline: 1.6666x; 1.5463x over previous
#include <cuda_runtime.h>
#include <cuda_fp16.h>
#include <math.h>
#include <stdint.h>

// Problem constants
#define BB    4
#define NQ    2048
#define NKV   4096
#define QDIM  512
#define KVDIM 128
#define NH    8
#define HD    64
#define INNER 512
// attention scale folded with log2(e): 0.125 * 1.4426950408889634
#define Q_PRESCALE 0.18033688011112042f

// ---------------------------------------------------------------------------
// Scratch. Q/K half [b][tok][h*64+d]; V half TRANSPOSED [b][h][d][key].
// ---------------------------------------------------------------------------
__device__ __half g_Qh[BB * NQ  * INNER];
__device__ __half g_Kh[BB * NKV * INNER];
__device__ __half g_Vh[BB * NKV * INNER];
__device__ float  g_AO[BB * NQ  * INNER];
// tf32-pre-rounded inputs for the projection GEMMs
__device__ float g_Rq [BB * NQ  * QDIM];
__device__ float g_Rkv[BB * NKV * KVDIM];
__device__ float g_Rwq[INNER * QDIM];
__device__ float g_Rwk[INNER * KVDIM];
__device__ float g_Rwv[INNER * KVDIM];
__device__ float g_Rwo[QDIM * INNER];

// ---------------------------------------------------------------------------
// Helpers
// ---------------------------------------------------------------------------
__device__ __forceinline__ uint32_t smem_u32(const void* p) {
    uint32_t a;
    asm("{ .reg .u64 t; cvta.to.shared.u64 t, %1; cvt.u32.u64 %0, t; }"
        : "=r"(a) : "l"(p));
    return a;
}
__device__ __forceinline__ void cp16(uint32_t dst, const void* src) {
    asm volatile("cp.async.cg.shared.global [%0], [%1], 16;\n"
                 :: "r"(dst), "l"(src));
}
#define CP_COMMIT() asm volatile("cp.async.commit_group;\n")
#define CP_WAIT1()  asm volatile("cp.async.wait_group 1;\n")
#define CP_WAIT0()  asm volatile("cp.async.wait_group 0;\n")

__device__ __forceinline__ uint32_t f2tf32(float x) {
    uint32_t r;
    asm("cvt.rna.tf32.f32 %0, %1;" : "=r"(r) : "f"(x));
    return r;
}
__device__ __forceinline__ float ex2(float x) {
    float r;
    asm("ex2.approx.f32 %0, %1;" : "=f"(r) : "f"(x));
    return r;
}
__device__ __forceinline__ void mma_tf32(float d[4], const uint32_t a[4],
                                         const uint32_t b[2], const float c[4]) {
    asm volatile(
        "mma.sync.aligned.m16n8k8.row.col.f32.tf32.tf32.f32 "
        "{%0,%1,%2,%3}, {%4,%5,%6,%7}, {%8,%9}, {%10,%11,%12,%13};\n"
        : "=f"(d[0]), "=f"(d[1]), "=f"(d[2]), "=f"(d[3])
        : "r"(a[0]), "r"(a[1]), "r"(a[2]), "r"(a[3]),
          "r"(b[0]), "r"(b[1]),
          "f"(c[0]), "f"(c[1]), "f"(c[2]), "f"(c[3]));
}
__device__ __forceinline__ void mma_f16(float d[4], const uint32_t a[4],
                                        const uint32_t b[2], const float c[4]) {
    asm volatile(
        "mma.sync.aligned.m16n8k16.row.col.f32.f16.f16.f32 "
        "{%0,%1,%2,%3}, {%4,%5,%6,%7}, {%8,%9}, {%10,%11,%12,%13};\n"
        : "=f"(d[0]), "=f"(d[1]), "=f"(d[2]), "=f"(d[3])
        : "r"(a[0]), "r"(a[1]), "r"(a[2]), "r"(a[3]),
          "r"(b[0]), "r"(b[1]),
          "f"(c[0]), "f"(c[1]), "f"(c[2]), "f"(c[3]));
}
__device__ __forceinline__ void ldsm4(uint32_t& r0, uint32_t& r1,
                                      uint32_t& r2, uint32_t& r3, uint32_t addr) {
    asm volatile("ldmatrix.sync.aligned.m8n8.x4.shared.b16 {%0,%1,%2,%3}, [%4];\n"
                 : "=r"(r0), "=r"(r1), "=r"(r2), "=r"(r3) : "r"(addr));
}

// ---------------------------------------------------------------------------
// Elementwise RNA tf32 rounding
// ---------------------------------------------------------------------------
__global__ __launch_bounds__(256) void round_tf32_kernel(
    const float* __restrict__ in, float* __restrict__ out, int n4)
{
    int i = blockIdx.x * 256 + threadIdx.x;
    if (i < n4) {
        float4 v = ((const float4*)in)[i];
        uint4 u = make_uint4(f2tf32(v.x), f2tf32(v.y), f2tf32(v.z), f2tf32(v.w));
        ((uint4*)out)[i] = u;
    }
}

// ---------------------------------------------------------------------------
// TF32 NT GEMM (operands pre-rounded): C = scale*(A @ W^T) (+ bias)
// OUT_MODE: 0 = fp32, 1 = tf32-rounded fp32, 2 = half, 3 = half scattered V^T
// ---------------------------------------------------------------------------
#define GBM 128
#define GBN 64
#define GBK 32
#define GSTR 36
#define GEMM_SMEM ((2*GBM*GSTR + 2*GBN*GSTR)*4)

template <bool HAS_BIAS, int OUT_MODE>
__global__ __launch_bounds__(256) void gemm_tf32_kernel(
    const float* __restrict__ A, const float* __restrict__ W,
    const float* __restrict__ bias, void* __restrict__ Cv,
    int M, int N, int K, float scale)
{
    extern __shared__ uint32_t gsm[];
    uint32_t* sA = gsm;
    uint32_t* sW = gsm + 2*GBM*GSTR;
    const uint32_t sA_u = smem_u32(sA);
    const uint32_t sW_u = smem_u32(sW);

    const int tid = threadIdx.x;
    const int lane = tid & 31, w = tid >> 5;
    const int g = lane >> 2, t = lane & 3;
    const int bm = blockIdx.y * GBM, bn = blockIdx.x * GBN;
    const int NIT = K / GBK;

    float acc[8][4];
#pragma unroll
    for (int nb = 0; nb < 8; nb++)
#pragma unroll
        for (int j = 0; j < 4; j++) acc[nb][j] = 0.f;

    {
#pragma unroll
        for (int i = 0; i < 4; i++) {
            int idx = tid + i*256, row = idx >> 3, c = idx & 7;
            cp16(sA_u + (row*GSTR + c*4)*4, A + (size_t)(bm + row)*K + c*4);
        }
#pragma unroll
        for (int i = 0; i < 2; i++) {
            int idx = tid + i*256, row = idx >> 3, c = idx & 7;
            cp16(sW_u + (row*GSTR + c*4)*4, W + (size_t)(bn + row)*K + c*4);
        }
        CP_COMMIT();
    }

    for (int it = 0; it < NIT; it++) {
        const int buf = it & 1;
        if (it + 1 < NIT) {
            const int k0 = (it + 1) * GBK, nb_ = (buf ^ 1);
#pragma unroll
            for (int i = 0; i < 4; i++) {
                int idx = tid + i*256, row = idx >> 3, c = idx & 7;
                cp16(sA_u + (nb_*GBM*GSTR + row*GSTR + c*4)*4,
                     A + (size_t)(bm + row)*K + k0 + c*4);
            }
#pragma unroll
            for (int i = 0; i < 2; i++) {
                int idx = tid + i*256, row = idx >> 3, c = idx & 7;
                cp16(sW_u + (nb_*GBN*GSTR + row*GSTR + c*4)*4,
                     W + (size_t)(bn + row)*K + k0 + c*4);
            }
            CP_COMMIT();
            CP_WAIT1();
        } else {
            CP_WAIT0();
        }
        __syncthreads();

        const uint32_t* tA = sA + buf*GBM*GSTR;
        const uint32_t* tW = sW + buf*GBN*GSTR;
#pragma unroll
        for (int ks = 0; ks < 4; ks++) {
            const int col = ks*8 + t;
            uint32_t a[4];
            a[0] = tA[(w*16 + g    )*GSTR + col];
            a[1] = tA[(w*16 + g + 8)*GSTR + col];
            a[2] = tA[(w*16 + g    )*GSTR + col + 4];
            a[3] = tA[(w*16 + g + 8)*GSTR + col + 4];
#pragma unroll
            for (int nb = 0; nb < 8; nb++) {
                uint32_t bfr[2];
                bfr[0] = tW[(nb*8 + g)*GSTR + col];
                bfr[1] = tW[(nb*8 + g)*GSTR + col + 4];
                mma_tf32(acc[nb], a, bfr, acc[nb]);
            }
        }
        __syncthreads();
    }

    const int r0 = bm + w*16 + g, r1 = r0 + 8;
#pragma unroll
    for (int nb = 0; nb < 8; nb++) {
        const int col = bn + nb*8 + 2*t;
        float v00 = acc[nb][0]*scale, v01 = acc[nb][1]*scale;
        float v10 = acc[nb][2]*scale, v11 = acc[nb][3]*scale;
        if (HAS_BIAS) {
            float b0 = bias[col], b1 = bias[col + 1];
            v00 += b0; v01 += b1; v10 += b0; v11 += b1;
        }
        if (OUT_MODE == 0 || OUT_MODE == 1) {
            float* C = (float*)Cv;
            if (OUT_MODE == 1) {
                v00 = __uint_as_float(f2tf32(v00)); v01 = __uint_as_float(f2tf32(v01));
                v10 = __uint_as_float(f2tf32(v10)); v11 = __uint_as_float(f2tf32(v11));
            }
            *(float2*)&C[(size_t)r0*N + col] = make_float2(v00, v01);
            *(float2*)&C[(size_t)r1*N + col] = make_float2(v10, v11);
        } else if (OUT_MODE == 2) {
            __half* C = (__half*)Cv;
            *(__half2*)&C[(size_t)r0*N + col] = __floats2half2_rn(v00, v01);
            *(__half2*)&C[(size_t)r1*N + col] = __floats2half2_rn(v10, v11);
        } else {
            // scatter into V^T [b][h][d][key]; rows are b*NKV+key, cols h*64+d
            __half* C = (__half*)Cv;
            int b_ = r0 >> 12;
            int key0 = r0 & (NKV - 1), key1 = r1 & (NKV - 1);
            size_t base0 = ((size_t)(b_*NH + (col >> 6))*HD + (col & 63)) * NKV;
            size_t base1 = base0 + NKV;
            C[base0 + key0] = __float2half_rn(v00);
            C[base1 + key0] = __float2half_rn(v01);
            C[base0 + key1] = __float2half_rn(v10);
            C[base1 + key1] = __float2half_rn(v11);
        }
    }
}

// ---------------------------------------------------------------------------
// Flash-attention core, fp16 operands + m16n8k16, fp32 accumulate.
// 4 warps x 32 q-rows, BQ=128, 128 threads, 2 CTAs/SM.
// smem halves, stride 72 (144B: rows hit disjoint bank quads for ldmatrix).
// ---------------------------------------------------------------------------
#define BQ    128
#define KT    64
#define STRH  72
#define NITA  (NKV / KT)
// K: 2 x 64 x 72 halves, V: same, QP: 128 x 72 halves
#define ATTN_SMEM ((2*KT*STRH + 2*KT*STRH + BQ*STRH) * 2)

__global__ __launch_bounds__(128, 2) void attn_mma_kernel()
{
    extern __shared__ __half smh[];
    __half* sK  = smh;                   // [2][64][72]  keys x d
    __half* sVt = sK + 2*KT*STRH;        // [2][64][72]  d x keys
    __half* sQP = sVt + 2*KT*STRH;       // [128][72]    Q staging, then P
    const uint32_t sK_u  = smem_u32(sK);
    const uint32_t sVt_u = smem_u32(sVt);
    const uint32_t sQP_u = smem_u32(sQP);

    const int qt = blockIdx.x, h = blockIdx.y, b = blockIdx.z;
    const int tid = threadIdx.x, lane = tid & 31, w = tid >> 5;
    const int g = lane >> 2, t = lane & 3;

    const __half* Qb  = g_Qh + (size_t)(b*NQ + qt*BQ)*INNER + h*HD;
    const __half* Kb  = g_Kh + (size_t)b*NKV*INNER + h*HD;
    const __half* Vtb = g_Vh + ((size_t)(b*NH + h)*HD)*NKV;

    // ldmatrix per-lane row/col bases (in halves)
    // K/V B-frags: m0/m1 = block rows 0-7 (col-half 0/8), m2/m3 = rows 8-15
    const int kvrow = ((lane >> 4)*8 + (lane & 7));
    const int kvcol = ((lane >> 3) & 1)*8;
    // P A-frags: lanes 0-15 -> rows 0-15 colbase 0; 16-31 -> rows 0-15 colbase 8
    const int prow = (lane & 15);
    const int pcol = (lane >> 4)*8;

    // ---- stage Q via cp.async (group 0): 128 rows x 64 halves ----
#pragma unroll
    for (int i = 0; i < 8; i++) {
        int idx = tid + i*128, row = idx >> 3, c = idx & 7;
        cp16(sQP_u + (row*STRH + c*8)*2, Qb + (size_t)row*INNER + c*8);
    }
    CP_COMMIT();

    // ---- first K/V^T tile (group 1): 64 rows x 64 halves each ----
#pragma unroll
    for (int i = 0; i < 4; i++) {
        int idx = tid + i*128, row = idx >> 3, c = idx & 7;
        cp16(sK_u  + (row*STRH + c*8)*2, Kb  + (size_t)row*INNER + c*8);
        cp16(sVt_u + (row*STRH + c*8)*2, Vtb + (size_t)row*NKV   + c*8);
    }
    CP_COMMIT();

    CP_WAIT1();
    __syncthreads();

    // ---- lift Q fragments (m16n8k16 A-layout), both row-blocks ----
    uint32_t qa[2][4][4];
#pragma unroll
    for (int r = 0; r < 2; r++)
#pragma unroll
        for (int ks = 0; ks < 4; ks++) {
            const int row = w*32 + r*16;
            const int c0 = ks*16 + 2*t;
            qa[r][ks][0] = *(const uint32_t*)&sQP[(row + g    )*STRH + c0];
            qa[r][ks][1] = *(const uint32_t*)&sQP[(row + g + 8)*STRH + c0];
            qa[r][ks][2] = *(const uint32_t*)&sQP[(row + g    )*STRH + c0 + 8];
            qa[r][ks][3] = *(const uint32_t*)&sQP[(row + g + 8)*STRH + c0 + 8];
        }

    float m0[2], m1[2], l0[2], l1[2];
#pragma unroll
    for (int r = 0; r < 2; r++) { m0[r] = m1[r] = -INFINITY; l0[r] = l1[r] = 0.f; }
    float o[2][8][4];
#pragma unroll
    for (int r = 0; r < 2; r++)
#pragma unroll
        for (int db = 0; db < 8; db++)
#pragma unroll
            for (int j = 0; j < 4; j++) o[r][db][j] = 0.f;

    __half* sPw = sQP + (w*32)*STRH;
    const uint32_t sPw_u = sQP_u + (w*32)*STRH*2;

    for (int it = 0; it < NITA; it++) {
        const int buf = it & 1;
        if (it + 1 < NITA) {
            const int nbuf = buf ^ 1;
#pragma unroll
            for (int i = 0; i < 4; i++) {
                int idx = tid + i*128, row = idx >> 3, c = idx & 7;
                cp16(sK_u  + (nbuf*KT*STRH + row*STRH + c*8)*2,
                     Kb  + (size_t)((it + 1)*KT + row)*INNER + c*8);
                cp16(sVt_u + (nbuf*KT*STRH + row*STRH + c*8)*2,
                     Vtb + (size_t)row*NKV + (it + 1)*KT + c*8);
            }
            CP_COMMIT();
            CP_WAIT1();
        } else {
            CP_WAIT0();
        }
        __syncthreads();

        const uint32_t tK_u  = sK_u  + buf*KT*STRH*2;
        const uint32_t tVt_u = sVt_u + buf*KT*STRH*2;

        // ---- S = Q K^T : 4 k16-steps x 4 key-block-pairs ----
        float s[2][8][4];
#pragma unroll
        for (int r = 0; r < 2; r++)
#pragma unroll
            for (int nb = 0; nb < 8; nb++)
#pragma unroll
                for (int j = 0; j < 4; j++) s[r][nb][j] = 0.f;

#pragma unroll
        for (int ks = 0; ks < 4; ks++) {
#pragma unroll
            for (int p = 0; p < 4; p++) {
                uint32_t b0, b1, b2, b3;
                ldsm4(b0, b1, b2, b3,
                      tK_u + ((p*16 + kvrow)*STRH + ks*16 + kvcol)*2);
                uint32_t bl[2] = {b0, b1}, bh[2] = {b2, b3};
                mma_f16(s[0][2*p    ], qa[0][ks], bl, s[0][2*p    ]);
                mma_f16(s[0][2*p + 1], qa[0][ks], bh, s[0][2*p + 1]);
                mma_f16(s[1][2*p    ], qa[1][ks], bl, s[1][2*p    ]);
                mma_f16(s[1][2*p + 1], qa[1][ks], bh, s[1][2*p + 1]);
            }
        }

        // ---- online softmax (exp2 domain), per row-block ----
#pragma unroll
        for (int r = 0; r < 2; r++) {
            float rm0 = -INFINITY, rm1 = -INFINITY;
#pragma unroll
            for (int nb = 0; nb < 8; nb++) {
                rm0 = fmaxf(rm0, fmaxf(s[r][nb][0], s[r][nb][1]));
                rm1 = fmaxf(rm1, fmaxf(s[r][nb][2], s[r][nb][3]));
            }
            rm0 = fmaxf(rm0, __shfl_xor_sync(0xffffffffu, rm0, 1));
            rm0 = fmaxf(rm0, __shfl_xor_sync(0xffffffffu, rm0, 2));
            rm1 = fmaxf(rm1, __shfl_xor_sync(0xffffffffu, rm1, 1));
            rm1 = fmaxf(rm1, __shfl_xor_sync(0xffffffffu, rm1, 2));

            float mn0 = fmaxf(m0[r], rm0), mn1 = fmaxf(m1[r], rm1);
            float corr0 = ex2(m0[r] - mn0), corr1 = ex2(m1[r] - mn1);
            m0[r] = mn0; m1[r] = mn1;

            float rs0 = 0.f, rs1 = 0.f;
#pragma unroll
            for (int nb = 0; nb < 8; nb++) {
                s[r][nb][0] = ex2(s[r][nb][0] - mn0);
                s[r][nb][1] = ex2(s[r][nb][1] - mn0);
                s[r][nb][2] = ex2(s[r][nb][2] - mn1);
                s[r][nb][3] = ex2(s[r][nb][3] - mn1);
                rs0 += s[r][nb][0] + s[r][nb][1];
                rs1 += s[r][nb][2] + s[r][nb][3];
            }
            rs0 += __shfl_xor_sync(0xffffffffu, rs0, 1);
            rs0 += __shfl_xor_sync(0xffffffffu, rs0, 2);
            rs1 += __shfl_xor_sync(0xffffffffu, rs1, 1);
            rs1 += __shfl_xor_sync(0xffffffffu, rs1, 2);
            l0[r] = l0[r] * corr0 + rs0;
            l1[r] = l1[r] * corr1 + rs1;

#pragma unroll
            for (int db = 0; db < 8; db++) {
                o[r][db][0] *= corr0; o[r][db][1] *= corr0;
                o[r][db][2] *= corr1; o[r][db][3] *= corr1;
            }

            // P -> smem as half2 (RNA), rows of this warp's 32-row block
#pragma unroll
            for (int nb = 0; nb < 8; nb++) {
                *(__half2*)&sPw[(r*16 + g    )*STRH + nb*8 + 2*t] =
                    __floats2half2_rn(s[r][nb][0], s[r][nb][1]);
                *(__half2*)&sPw[(r*16 + g + 8)*STRH + nb*8 + 2*t] =
                    __floats2half2_rn(s[r][nb][2], s[r][nb][3]);
            }
        }
        __syncwarp();

        // ---- O += P V : 4 k16-steps (16 keys each) x 4 d-block-pairs ----
#pragma unroll
        for (int ks = 0; ks < 4; ks++) {
            uint32_t pa0[4], pa1[4];
            ldsm4(pa0[0], pa0[1], pa0[2], pa0[3],
                  sPw_u + ((prow     )*STRH + ks*16 + pcol)*2);
            ldsm4(pa1[0], pa1[1], pa1[2], pa1[3],
                  sPw_u + ((prow + 16)*STRH + ks*16 + pcol)*2);
#pragma unroll
            for (int p = 0; p < 4; p++) {
                uint32_t b0, b1, b2, b3;
                ldsm4(b0, b1, b2, b3,
                      tVt_u + ((p*16 + kvrow)*STRH + ks*16 + kvcol)*2);
                uint32_t bl[2] = {b0, b1}, bh[2] = {b2, b3};
                mma_f16(o[0][2*p    ], pa0, bl, o[0][2*p    ]);
                mma_f16(o[0][2*p + 1], pa0, bh, o[0][2*p + 1]);
                mma_f16(o[1][2*p    ], pa1, bl, o[1][2*p    ]);
                mma_f16(o[1][2*p + 1], pa1, bh, o[1][2*p + 1]);
            }
        }
        __syncthreads();
    }

    // ---- epilogue: normalize, tf32-round, write AO (fp32) ----
#pragma unroll
    for (int r = 0; r < 2; r++) {
        const float inv0 = 1.f / l0[r], inv1 = 1.f / l1[r];
        const int q0 = qt*BQ + w*32 + r*16 + g, q1 = q0 + 8;
#pragma unroll
        for (int db = 0; db < 8; db++) {
            uint2 r0v = make_uint2(f2tf32(o[r][db][0]*inv0), f2tf32(o[r][db][1]*inv0));
            uint2 r1v = make_uint2(f2tf32(o[r][db][2]*inv1), f2tf32(o[r][db][3]*inv1));
            *(uint2*)&g_AO[(size_t)(b*NQ + q0)*INNER + h*HD + db*8 + 2*t] = r0v;
            *(uint2*)&g_AO[(size_t)(b*NQ + q1)*INNER + h*HD + db*8 + 2*t] = r1v;
        }
    }
}

// ---------------------------------------------------------------------------
// Launch
// ---------------------------------------------------------------------------
extern "C" void kernel_launch(void* const* d_in, const int* in_sizes, int n_in,
                              void* d_out, int out_size)
{
    const float* q   = (const float*)d_in[0];
    const float* kv  = (const float*)d_in[1];
    const float* w_q = (const float*)d_in[2];
    const float* w_k = (const float*)d_in[3];
    const float* w_v = (const float*)d_in[4];
    const float* w_o = (const float*)d_in[5];
    const float* b_o = (const float*)d_in[6];
    float* out = (float*)d_out;

    void *Qh, *Kh, *Vh, *AO, *Rq, *Rkv, *Rwq, *Rwk, *Rwv, *Rwo;
    cudaGetSymbolAddress(&Qh,  g_Qh);
    cudaGetSymbolAddress(&Kh,  g_Kh);
    cudaGetSymbolAddress(&Vh,  g_Vh);
    cudaGetSymbolAddress(&AO,  g_AO);
    cudaGetSymbolAddress(&Rq,  g_Rq);
    cudaGetSymbolAddress(&Rkv, g_Rkv);
    cudaGetSymbolAddress(&Rwq, g_Rwq);
    cudaGetSymbolAddress(&Rwk, g_Rwk);
    cudaGetSymbolAddress(&Rwv, g_Rwv);
    cudaGetSymbolAddress(&Rwo, g_Rwo);

    const int MQ = BB * NQ;    // 8192
    const int MK = BB * NKV;   // 16384

    cudaFuncSetAttribute(gemm_tf32_kernel<false, 2>,
                         cudaFuncAttributeMaxDynamicSharedMemorySize, GEMM_SMEM);
    cudaFuncSetAttribute(gemm_tf32_kernel<false, 3>,
                         cudaFuncAttributeMaxDynamicSharedMemorySize, GEMM_SMEM);
    cudaFuncSetAttribute(gemm_tf32_kernel<true, 0>,
                         cudaFuncAttributeMaxDynamicSharedMemorySize, GEMM_SMEM);
    cudaFuncSetAttribute(attn_mma_kernel,
                         cudaFuncAttributeMaxDynamicSharedMemorySize, ATTN_SMEM);

    // ---- pre-round GEMM inputs to tf32 ----
    {
        int n;
        n = MQ*QDIM/4;      round_tf32_kernel<<<(n+255)/256, 256>>>(q,   (float*)Rq,  n);
        n = MK*KVDIM/4;     round_tf32_kernel<<<(n+255)/256, 256>>>(kv,  (float*)Rkv, n);
        n = INNER*QDIM/4;   round_tf32_kernel<<<(n+255)/256, 256>>>(w_q, (float*)Rwq, n);
        n = INNER*KVDIM/4;  round_tf32_kernel<<<(n+255)/256, 256>>>(w_k, (float*)Rwk, n);
        n = INNER*KVDIM/4;  round_tf32_kernel<<<(n+255)/256, 256>>>(w_v, (float*)Rwv, n);
        n = QDIM*INNER/4;   round_tf32_kernel<<<(n+255)/256, 256>>>(w_o, (float*)Rwo, n);
    }

    // Q projection -> half, pre-scaled by 0.125*log2(e)
    gemm_tf32_kernel<false, 2><<<dim3(INNER/GBN, MQ/GBM), 256, GEMM_SMEM>>>(
        (float*)Rq, (float*)Rwq, nullptr, Qh, MQ, INNER, QDIM, Q_PRESCALE);
    // K projection -> half
    gemm_tf32_kernel<false, 2><<<dim3(INNER/GBN, MK/GBM), 256, GEMM_SMEM>>>(
        (float*)Rkv, (float*)Rwk, nullptr, Kh, MK, INNER, KVDIM, 1.0f);
    // V projection -> half, scattered transposed [b][h][d][key]
    gemm_tf32_kernel<false, 3><<<dim3(INNER/GBN, MK/GBM), 256, GEMM_SMEM>>>(
        (float*)Rkv, (float*)Rwv, nullptr, Vh, MK, INNER, KVDIM, 1.0f);

    attn_mma_kernel<<<dim3(NQ/BQ, NH, BB), 128, ATTN_SMEM>>>();

    // Output projection: fp32 epilogue + bias (AO tf32-pre-rounded)
    gemm_tf32_kernel<true, 0><<<dim3(QDIM/GBN, MQ/GBM), 256, GEMM_SMEM>>>(
        (float*)AO, (float*)Rwo, b_o, out, MQ, QDIM, INNER, 1.0f);
}

// round 11
// speedup vs baseline: 1.9419x; 1.1652x over previous
#include <cuda_runtime.h>
#include <cuda_fp16.h>
#include <math.h>
#include <stdint.h>

// Problem constants
#define BB    4
#define NQ    2048
#define NKV   4096
#define QDIM  512
#define KVDIM 128
#define NH    8
#define HD    64
#define INNER 512
// attention scale folded with log2(e): 0.125 * 1.4426950408889634
#define Q_PRESCALE 0.18033688011112042f

// ---------------------------------------------------------------------------
// Scratch. Q/K half [b][tok][h*64+d]; V half TRANSPOSED [b][h][d][key];
// AO half (feeds fp16 O-projection). All GEMM inputs pre-rounded to half.
// ---------------------------------------------------------------------------
__device__ __half g_Qh [BB * NQ  * INNER];
__device__ __half g_Kh [BB * NKV * INNER];
__device__ __half g_Vh [BB * NKV * INNER];
__device__ __half g_AOh[BB * NQ  * INNER];
__device__ __half g_Rq [BB * NQ  * QDIM];
__device__ __half g_Rkv[BB * NKV * KVDIM];
__device__ __half g_Rwq[INNER * QDIM];
__device__ __half g_Rwk[INNER * KVDIM];
__device__ __half g_Rwv[INNER * KVDIM];
__device__ __half g_Rwo[QDIM * INNER];

// ---------------------------------------------------------------------------
// Helpers
// ---------------------------------------------------------------------------
__device__ __forceinline__ uint32_t smem_u32(const void* p) {
    uint32_t a;
    asm("{ .reg .u64 t; cvta.to.shared.u64 t, %1; cvt.u32.u64 %0, t; }"
        : "=r"(a) : "l"(p));
    return a;
}
__device__ __forceinline__ void cp16(uint32_t dst, const void* src) {
    asm volatile("cp.async.cg.shared.global [%0], [%1], 16;\n"
                 :: "r"(dst), "l"(src));
}
#define CP_COMMIT() asm volatile("cp.async.commit_group;\n")
#define CP_WAIT1()  asm volatile("cp.async.wait_group 1;\n")
#define CP_WAIT0()  asm volatile("cp.async.wait_group 0;\n")

__device__ __forceinline__ float ex2(float x) {
    float r;
    asm("ex2.approx.f32 %0, %1;" : "=f"(r) : "f"(x));
    return r;
}
__device__ __forceinline__ void mma_f16(float d[4], const uint32_t a[4],
                                        const uint32_t b[2], const float c[4]) {
    asm volatile(
        "mma.sync.aligned.m16n8k16.row.col.f32.f16.f16.f32 "
        "{%0,%1,%2,%3}, {%4,%5,%6,%7}, {%8,%9}, {%10,%11,%12,%13};\n"
        : "=f"(d[0]), "=f"(d[1]), "=f"(d[2]), "=f"(d[3])
        : "r"(a[0]), "r"(a[1]), "r"(a[2]), "r"(a[3]),
          "r"(b[0]), "r"(b[1]),
          "f"(c[0]), "f"(c[1]), "f"(c[2]), "f"(c[3]));
}
__device__ __forceinline__ void ldsm4(uint32_t& r0, uint32_t& r1,
                                      uint32_t& r2, uint32_t& r3, uint32_t addr) {
    asm volatile("ldmatrix.sync.aligned.m8n8.x4.shared.b16 {%0,%1,%2,%3}, [%4];\n"
                 : "=r"(r0), "=r"(r1), "=r"(r2), "=r"(r3) : "r"(addr));
}

// ---------------------------------------------------------------------------
// Elementwise fp32 -> fp16 rounding (RNA; 10-bit mantissa, same as tf32)
// ---------------------------------------------------------------------------
__global__ __launch_bounds__(256) void round_f16_kernel(
    const float* __restrict__ in, __half* __restrict__ out, int n4)
{
    int i = blockIdx.x * 256 + threadIdx.x;
    if (i < n4) {
        float4 v = ((const float4*)in)[i];
        __half2 lo = __floats2half2_rn(v.x, v.y);
        __half2 hi = __floats2half2_rn(v.z, v.w);
        uint2 u;
        u.x = *(uint32_t*)&lo; u.y = *(uint32_t*)&hi;
        ((uint2*)out)[i] = u;
    }
}

// ---------------------------------------------------------------------------
// FP16 NT GEMM: C = scale*(A[M,K] @ W[N,K]^T) (+ bias), fp32 accumulate.
// Tile 128x64x64, 128 threads = 4 warps x 32 rows; ldmatrix A and B frags.
// OUT_MODE: 0 = fp32, 2 = half, 3 = half scattered V^T [b][h][d][key]
// ---------------------------------------------------------------------------
#define GSTR 72
#define GEMM_SMEM ((2*128*GSTR + 2*64*GSTR) * 2)

template <bool HAS_BIAS, int OUT_MODE>
__global__ __launch_bounds__(128) void gemm_f16_kernel(
    const __half* __restrict__ A, const __half* __restrict__ W,
    const float* __restrict__ bias, void* __restrict__ Cv,
    int M, int N, int K, float scale)
{
    extern __shared__ __half gsh[];
    __half* sA = gsh;                    // [2][128][72]
    __half* sW = gsh + 2*128*GSTR;       // [2][64][72]
    const uint32_t sA_u = smem_u32(sA);
    const uint32_t sW_u = smem_u32(sW);

    const int tid = threadIdx.x;
    const int lane = tid & 31, w = tid >> 5;
    const int g = lane >> 2, t = lane & 3;
    const int bm = blockIdx.y * 128, bn = blockIdx.x * 64;
    const int NIT = K / 64;

    // ldmatrix lane maps (validated in R10 attention kernel)
    const int arow = (lane & 15), acol = (lane >> 4)*8;           // A frags
    const int brow = ((lane >> 4)*8 + (lane & 7));                // B frags
    const int bcol = ((lane >> 3) & 1)*8;

    float acc[2][8][4];
#pragma unroll
    for (int r = 0; r < 2; r++)
#pragma unroll
        for (int nb = 0; nb < 8; nb++)
#pragma unroll
            for (int j = 0; j < 4; j++) acc[r][nb][j] = 0.f;

    // prologue: tile 0 -> buf 0   (A: 1024 cp16, W: 512 cp16)
    {
#pragma unroll
        for (int i = 0; i < 8; i++) {
            int idx = tid + i*128, row = idx >> 3, c = idx & 7;
            cp16(sA_u + (row*GSTR + c*8)*2, A + (size_t)(bm + row)*K + c*8);
        }
#pragma unroll
        for (int i = 0; i < 4; i++) {
            int idx = tid + i*128, row = idx >> 3, c = idx & 7;
            cp16(sW_u + (row*GSTR + c*8)*2, W + (size_t)(bn + row)*K + c*8);
        }
        CP_COMMIT();
    }

    for (int it = 0; it < NIT; it++) {
        const int buf = it & 1;
        if (it + 1 < NIT) {
            const int k0 = (it + 1) * 64, nbuf = buf ^ 1;
#pragma unroll
            for (int i = 0; i < 8; i++) {
                int idx = tid + i*128, row = idx >> 3, c = idx & 7;
                cp16(sA_u + (nbuf*128*GSTR + row*GSTR + c*8)*2,
                     A + (size_t)(bm + row)*K + k0 + c*8);
            }
#pragma unroll
            for (int i = 0; i < 4; i++) {
                int idx = tid + i*128, row = idx >> 3, c = idx & 7;
                cp16(sW_u + (nbuf*64*GSTR + row*GSTR + c*8)*2,
                     W + (size_t)(bn + row)*K + k0 + c*8);
            }
            CP_COMMIT();
            CP_WAIT1();
        } else {
            CP_WAIT0();
        }
        __syncthreads();

        const uint32_t tA_u = sA_u + buf*128*GSTR*2;
        const uint32_t tW_u = sW_u + buf*64*GSTR*2;

#pragma unroll
        for (int ks = 0; ks < 4; ks++) {
            uint32_t a0[4], a1[4];
            ldsm4(a0[0], a0[1], a0[2], a0[3],
                  tA_u + ((w*32 + arow)*GSTR + ks*16 + acol)*2);
            ldsm4(a1[0], a1[1], a1[2], a1[3],
                  tA_u + ((w*32 + 16 + arow)*GSTR + ks*16 + acol)*2);
#pragma unroll
            for (int p = 0; p < 4; p++) {
                uint32_t b0, b1, b2, b3;
                ldsm4(b0, b1, b2, b3,
                      tW_u + ((p*16 + brow)*GSTR + ks*16 + bcol)*2);
                uint32_t bl[2] = {b0, b1}, bh[2] = {b2, b3};
                mma_f16(acc[0][2*p    ], a0, bl, acc[0][2*p    ]);
                mma_f16(acc[0][2*p + 1], a0, bh, acc[0][2*p + 1]);
                mma_f16(acc[1][2*p    ], a1, bl, acc[1][2*p    ]);
                mma_f16(acc[1][2*p + 1], a1, bh, acc[1][2*p + 1]);
            }
        }
        __syncthreads();
    }

#pragma unroll
    for (int r = 0; r < 2; r++) {
        const int r0 = bm + w*32 + r*16 + g, r1 = r0 + 8;
#pragma unroll
        for (int nb = 0; nb < 8; nb++) {
            const int col = bn + nb*8 + 2*t;
            float v00 = acc[r][nb][0]*scale, v01 = acc[r][nb][1]*scale;
            float v10 = acc[r][nb][2]*scale, v11 = acc[r][nb][3]*scale;
            if (HAS_BIAS) {
                float b0 = bias[col], b1 = bias[col + 1];
                v00 += b0; v01 += b1; v10 += b0; v11 += b1;
            }
            if (OUT_MODE == 0) {
                float* C = (float*)Cv;
                *(float2*)&C[(size_t)r0*N + col] = make_float2(v00, v01);
                *(float2*)&C[(size_t)r1*N + col] = make_float2(v10, v11);
            } else if (OUT_MODE == 2) {
                __half* C = (__half*)Cv;
                *(__half2*)&C[(size_t)r0*N + col] = __floats2half2_rn(v00, v01);
                *(__half2*)&C[(size_t)r1*N + col] = __floats2half2_rn(v10, v11);
            } else {
                // scatter into V^T [b][h][d][key]; rows b*NKV+key, cols h*64+d
                __half* C = (__half*)Cv;
                int b_ = r0 >> 12;
                int key0 = r0 & (NKV - 1), key1 = r1 & (NKV - 1);
                size_t base0 = ((size_t)(b_*NH + (col >> 6))*HD + (col & 63)) * NKV;
                size_t base1 = base0 + NKV;
                C[base0 + key0] = __float2half_rn(v00);
                C[base1 + key0] = __float2half_rn(v01);
                C[base0 + key1] = __float2half_rn(v10);
                C[base1 + key1] = __float2half_rn(v11);
            }
        }
    }
}

// ---------------------------------------------------------------------------
// Flash-attention core, fp16 operands + m16n8k16, fp32 accumulate.
// 4 warps x 32 q-rows, BQ=128, 128 threads, 2 CTAs/SM.  (unchanged from R10
// except epilogue emits half into g_AOh)
// ---------------------------------------------------------------------------
#define BQ    128
#define KT    64
#define STRH  72
#define NITA  (NKV / KT)
#define ATTN_SMEM ((2*KT*STRH + 2*KT*STRH + BQ*STRH) * 2)

__global__ __launch_bounds__(128, 2) void attn_mma_kernel()
{
    extern __shared__ __half smh[];
    __half* sK  = smh;                   // [2][64][72]  keys x d
    __half* sVt = sK + 2*KT*STRH;        // [2][64][72]  d x keys
    __half* sQP = sVt + 2*KT*STRH;       // [128][72]    Q staging, then P
    const uint32_t sK_u  = smem_u32(sK);
    const uint32_t sVt_u = smem_u32(sVt);
    const uint32_t sQP_u = smem_u32(sQP);

    const int qt = blockIdx.x, h = blockIdx.y, b = blockIdx.z;
    const int tid = threadIdx.x, lane = tid & 31, w = tid >> 5;
    const int g = lane >> 2, t = lane & 3;

    const __half* Qb  = g_Qh + (size_t)(b*NQ + qt*BQ)*INNER + h*HD;
    const __half* Kb  = g_Kh + (size_t)b*NKV*INNER + h*HD;
    const __half* Vtb = g_Vh + ((size_t)(b*NH + h)*HD)*NKV;

    const int kvrow = ((lane >> 4)*8 + (lane & 7));
    const int kvcol = ((lane >> 3) & 1)*8;
    const int prow = (lane & 15);
    const int pcol = (lane >> 4)*8;

    // ---- stage Q via cp.async (group 0) ----
#pragma unroll
    for (int i = 0; i < 8; i++) {
        int idx = tid + i*128, row = idx >> 3, c = idx & 7;
        cp16(sQP_u + (row*STRH + c*8)*2, Qb + (size_t)row*INNER + c*8);
    }
    CP_COMMIT();

    // ---- first K/V^T tile (group 1) ----
#pragma unroll
    for (int i = 0; i < 4; i++) {
        int idx = tid + i*128, row = idx >> 3, c = idx & 7;
        cp16(sK_u  + (row*STRH + c*8)*2, Kb  + (size_t)row*INNER + c*8);
        cp16(sVt_u + (row*STRH + c*8)*2, Vtb + (size_t)row*NKV   + c*8);
    }
    CP_COMMIT();

    CP_WAIT1();
    __syncthreads();

    // ---- lift Q fragments (m16n8k16 A-layout), both row-blocks ----
    uint32_t qa[2][4][4];
#pragma unroll
    for (int r = 0; r < 2; r++)
#pragma unroll
        for (int ks = 0; ks < 4; ks++) {
            const int row = w*32 + r*16;
            const int c0 = ks*16 + 2*t;
            qa[r][ks][0] = *(const uint32_t*)&sQP[(row + g    )*STRH + c0];
            qa[r][ks][1] = *(const uint32_t*)&sQP[(row + g + 8)*STRH + c0];
            qa[r][ks][2] = *(const uint32_t*)&sQP[(row + g    )*STRH + c0 + 8];
            qa[r][ks][3] = *(const uint32_t*)&sQP[(row + g + 8)*STRH + c0 + 8];
        }

    float m0[2], m1[2], l0[2], l1[2];
#pragma unroll
    for (int r = 0; r < 2; r++) { m0[r] = m1[r] = -INFINITY; l0[r] = l1[r] = 0.f; }
    float o[2][8][4];
#pragma unroll
    for (int r = 0; r < 2; r++)
#pragma unroll
        for (int db = 0; db < 8; db++)
#pragma unroll
            for (int j = 0; j < 4; j++) o[r][db][j] = 0.f;

    __half* sPw = sQP + (w*32)*STRH;
    const uint32_t sPw_u = sQP_u + (w*32)*STRH*2;

    for (int it = 0; it < NITA; it++) {
        const int buf = it & 1;
        if (it + 1 < NITA) {
            const int nbuf = buf ^ 1;
#pragma unroll
            for (int i = 0; i < 4; i++) {
                int idx = tid + i*128, row = idx >> 3, c = idx & 7;
                cp16(sK_u  + (nbuf*KT*STRH + row*STRH + c*8)*2,
                     Kb  + (size_t)((it + 1)*KT + row)*INNER + c*8);
                cp16(sVt_u + (nbuf*KT*STRH + row*STRH + c*8)*2,
                     Vtb + (size_t)row*NKV + (it + 1)*KT + c*8);
            }
            CP_COMMIT();
            CP_WAIT1();
        } else {
            CP_WAIT0();
        }
        __syncthreads();

        const uint32_t tK_u  = sK_u  + buf*KT*STRH*2;
        const uint32_t tVt_u = sVt_u + buf*KT*STRH*2;

        // ---- S = Q K^T ----
        float s[2][8][4];
#pragma unroll
        for (int r = 0; r < 2; r++)
#pragma unroll
            for (int nb = 0; nb < 8; nb++)
#pragma unroll
                for (int j = 0; j < 4; j++) s[r][nb][j] = 0.f;

#pragma unroll
        for (int ks = 0; ks < 4; ks++) {
#pragma unroll
            for (int p = 0; p < 4; p++) {
                uint32_t b0, b1, b2, b3;
                ldsm4(b0, b1, b2, b3,
                      tK_u + ((p*16 + kvrow)*STRH + ks*16 + kvcol)*2);
                uint32_t bl[2] = {b0, b1}, bh[2] = {b2, b3};
                mma_f16(s[0][2*p    ], qa[0][ks], bl, s[0][2*p    ]);
                mma_f16(s[0][2*p + 1], qa[0][ks], bh, s[0][2*p + 1]);
                mma_f16(s[1][2*p    ], qa[1][ks], bl, s[1][2*p    ]);
                mma_f16(s[1][2*p + 1], qa[1][ks], bh, s[1][2*p + 1]);
            }
        }

        // ---- online softmax (exp2 domain) ----
#pragma unroll
        for (int r = 0; r < 2; r++) {
            float rm0 = -INFINITY, rm1 = -INFINITY;
#pragma unroll
            for (int nb = 0; nb < 8; nb++) {
                rm0 = fmaxf(rm0, fmaxf(s[r][nb][0], s[r][nb][1]));
                rm1 = fmaxf(rm1, fmaxf(s[r][nb][2], s[r][nb][3]));
            }
            rm0 = fmaxf(rm0, __shfl_xor_sync(0xffffffffu, rm0, 1));
            rm0 = fmaxf(rm0, __shfl_xor_sync(0xffffffffu, rm0, 2));
            rm1 = fmaxf(rm1, __shfl_xor_sync(0xffffffffu, rm1, 1));
            rm1 = fmaxf(rm1, __shfl_xor_sync(0xffffffffu, rm1, 2));

            float mn0 = fmaxf(m0[r], rm0), mn1 = fmaxf(m1[r], rm1);
            float corr0 = ex2(m0[r] - mn0), corr1 = ex2(m1[r] - mn1);
            m0[r] = mn0; m1[r] = mn1;

            float rs0 = 0.f, rs1 = 0.f;
#pragma unroll
            for (int nb = 0; nb < 8; nb++) {
                s[r][nb][0] = ex2(s[r][nb][0] - mn0);
                s[r][nb][1] = ex2(s[r][nb][1] - mn0);
                s[r][nb][2] = ex2(s[r][nb][2] - mn1);
                s[r][nb][3] = ex2(s[r][nb][3] - mn1);
                rs0 += s[r][nb][0] + s[r][nb][1];
                rs1 += s[r][nb][2] + s[r][nb][3];
            }
            rs0 += __shfl_xor_sync(0xffffffffu, rs0, 1);
            rs0 += __shfl_xor_sync(0xffffffffu, rs0, 2);
            rs1 += __shfl_xor_sync(0xffffffffu, rs1, 1);
            rs1 += __shfl_xor_sync(0xffffffffu, rs1, 2);
            l0[r] = l0[r] * corr0 + rs0;
            l1[r] = l1[r] * corr1 + rs1;

#pragma unroll
            for (int db = 0; db < 8; db++) {
                o[r][db][0] *= corr0; o[r][db][1] *= corr0;
                o[r][db][2] *= corr1; o[r][db][3] *= corr1;
            }

            // P -> smem as half2
#pragma unroll
            for (int nb = 0; nb < 8; nb++) {
                *(__half2*)&sPw[(r*16 + g    )*STRH + nb*8 + 2*t] =
                    __floats2half2_rn(s[r][nb][0], s[r][nb][1]);
                *(__half2*)&sPw[(r*16 + g + 8)*STRH + nb*8 + 2*t] =
                    __floats2half2_rn(s[r][nb][2], s[r][nb][3]);
            }
        }
        __syncwarp();

        // ---- O += P V ----
#pragma unroll
        for (int ks = 0; ks < 4; ks++) {
            uint32_t pa0[4], pa1[4];
            ldsm4(pa0[0], pa0[1], pa0[2], pa0[3],
                  sPw_u + ((prow     )*STRH + ks*16 + pcol)*2);
            ldsm4(pa1[0], pa1[1], pa1[2], pa1[3],
                  sPw_u + ((prow + 16)*STRH + ks*16 + pcol)*2);
#pragma unroll
            for (int p = 0; p < 4; p++) {
                uint32_t b0, b1, b2, b3;
                ldsm4(b0, b1, b2, b3,
                      tVt_u + ((p*16 + kvrow)*STRH + ks*16 + kvcol)*2);
                uint32_t bl[2] = {b0, b1}, bh[2] = {b2, b3};
                mma_f16(o[0][2*p    ], pa0, bl, o[0][2*p    ]);
                mma_f16(o[0][2*p + 1], pa0, bh, o[0][2*p + 1]);
                mma_f16(o[1][2*p    ], pa1, bl, o[1][2*p    ]);
                mma_f16(o[1][2*p + 1], pa1, bh, o[1][2*p + 1]);
            }
        }
        __syncthreads();
    }

    // ---- epilogue: normalize, write AO as half (feeds fp16 O-proj) ----
#pragma unroll
    for (int r = 0; r < 2; r++) {
        const float inv0 = 1.f / l0[r], inv1 = 1.f / l1[r];
        const int q0 = qt*BQ + w*32 + r*16 + g, q1 = q0 + 8;
#pragma unroll
        for (int db = 0; db < 8; db++) {
            *(__half2*)&g_AOh[(size_t)(b*NQ + q0)*INNER + h*HD + db*8 + 2*t] =
                __floats2half2_rn(o[r][db][0]*inv0, o[r][db][1]*inv0);
            *(__half2*)&g_AOh[(size_t)(b*NQ + q1)*INNER + h*HD + db*8 + 2*t] =
                __floats2half2_rn(o[r][db][2]*inv1, o[r][db][3]*inv1);
        }
    }
}

// ---------------------------------------------------------------------------
// Launch
// ---------------------------------------------------------------------------
extern "C" void kernel_launch(void* const* d_in, const int* in_sizes, int n_in,
                              void* d_out, int out_size)
{
    const float* q   = (const float*)d_in[0];
    const float* kv  = (const float*)d_in[1];
    const float* w_q = (const float*)d_in[2];
    const float* w_k = (const float*)d_in[3];
    const float* w_v = (const float*)d_in[4];
    const float* w_o = (const float*)d_in[5];
    const float* b_o = (const float*)d_in[6];
    float* out = (float*)d_out;

    void *Qh, *Kh, *Vh, *AOh, *Rq, *Rkv, *Rwq, *Rwk, *Rwv, *Rwo;
    cudaGetSymbolAddress(&Qh,  g_Qh);
    cudaGetSymbolAddress(&Kh,  g_Kh);
    cudaGetSymbolAddress(&Vh,  g_Vh);
    cudaGetSymbolAddress(&AOh, g_AOh);
    cudaGetSymbolAddress(&Rq,  g_Rq);
    cudaGetSymbolAddress(&Rkv, g_Rkv);
    cudaGetSymbolAddress(&Rwq, g_Rwq);
    cudaGetSymbolAddress(&Rwk, g_Rwk);
    cudaGetSymbolAddress(&Rwv, g_Rwv);
    cudaGetSymbolAddress(&Rwo, g_Rwo);

    const int MQ = BB * NQ;    // 8192
    const int MK = BB * NKV;   // 16384

    cudaFuncSetAttribute(gemm_f16_kernel<false, 2>,
                         cudaFuncAttributeMaxDynamicSharedMemorySize, GEMM_SMEM);
    cudaFuncSetAttribute(gemm_f16_kernel<false, 3>,
                         cudaFuncAttributeMaxDynamicSharedMemorySize, GEMM_SMEM);
    cudaFuncSetAttribute(gemm_f16_kernel<true, 0>,
                         cudaFuncAttributeMaxDynamicSharedMemorySize, GEMM_SMEM);
    cudaFuncSetAttribute(attn_mma_kernel,
                         cudaFuncAttributeMaxDynamicSharedMemorySize, ATTN_SMEM);

    // ---- pre-round GEMM inputs to fp16 (RNA; same mantissa as tf32) ----
    {
        int n;
        n = MQ*QDIM/4;      round_f16_kernel<<<(n+255)/256, 256>>>(q,   (__half*)Rq,  n);
        n = MK*KVDIM/4;     round_f16_kernel<<<(n+255)/256, 256>>>(kv,  (__half*)Rkv, n);
        n = INNER*QDIM/4;   round_f16_kernel<<<(n+255)/256, 256>>>(w_q, (__half*)Rwq, n);
        n = INNER*KVDIM/4;  round_f16_kernel<<<(n+255)/256, 256>>>(w_k, (__half*)Rwk, n);
        n = INNER*KVDIM/4;  round_f16_kernel<<<(n+255)/256, 256>>>(w_v, (__half*)Rwv, n);
        n = QDIM*INNER/4;   round_f16_kernel<<<(n+255)/256, 256>>>(w_o, (__half*)Rwo, n);
    }

    // Q projection -> half, pre-scaled by 0.125*log2(e)
    gemm_f16_kernel<false, 2><<<dim3(INNER/64, MQ/128), 128, GEMM_SMEM>>>(
        (__half*)Rq, (__half*)Rwq, nullptr, Qh, MQ, INNER, QDIM, Q_PRESCALE);
    // K projection -> half
    gemm_f16_kernel<false, 2><<<dim3(INNER/64, MK/128), 128, GEMM_SMEM>>>(
        (__half*)Rkv, (__half*)Rwk, nullptr, Kh, MK, INNER, KVDIM, 1.0f);
    // V projection -> half, scattered transposed [b][h][d][key]
    gemm_f16_kernel<false, 3><<<dim3(INNER/64, MK/128), 128, GEMM_SMEM>>>(
        (__half*)Rkv, (__half*)Rwv, nullptr, Vh, MK, INNER, KVDIM, 1.0f);

    attn_mma_kernel<<<dim3(NQ/BQ, NH, BB), 128, ATTN_SMEM>>>();

    // Output projection: fp32 epilogue + bias
    gemm_f16_kernel<true, 0><<<dim3(QDIM/64, MQ/128), 128, GEMM_SMEM>>>(
        (__half*)AOh, (__half*)Rwo, b_o, out, MQ, QDIM, INNER, 1.0f);
}

// round 12
// speedup vs baseline: 1.9825x; 1.0209x over previous
#include <cuda_runtime.h>
#include <cuda_fp16.h>
#include <math.h>
#include <stdint.h>

// Problem constants
#define BB    4
#define NQ    2048
#define NKV   4096
#define QDIM  512
#define KVDIM 128
#define NH    8
#define HD    64
#define INNER 512
// attention scale folded with log2(e): 0.125 * 1.4426950408889634
#define Q_PRESCALE 0.18033688011112042f

// ---------------------------------------------------------------------------
// Scratch. Q/K half [b][tok][h*64+d]; V half TRANSPOSED [b][h][d][key];
// AO half (feeds fp16 O-projection). All GEMM inputs pre-rounded to half.
// ---------------------------------------------------------------------------
__device__ __half g_Qh [BB * NQ  * INNER];
__device__ __half g_Kh [BB * NKV * INNER];
__device__ __half g_Vh [BB * NKV * INNER];
__device__ __half g_AOh[BB * NQ  * INNER];
__device__ __half g_Rq [BB * NQ  * QDIM];
__device__ __half g_Rkv[BB * NKV * KVDIM];
__device__ __half g_Rwq[INNER * QDIM];
__device__ __half g_Rwk[INNER * KVDIM];
__device__ __half g_Rwv[INNER * KVDIM];
__device__ __half g_Rwo[QDIM * INNER];

// ---------------------------------------------------------------------------
// Helpers
// ---------------------------------------------------------------------------
__device__ __forceinline__ uint32_t smem_u32(const void* p) {
    uint32_t a;
    asm("{ .reg .u64 t; cvta.to.shared.u64 t, %1; cvt.u32.u64 %0, t; }"
        : "=r"(a) : "l"(p));
    return a;
}
__device__ __forceinline__ void cp16(uint32_t dst, const void* src) {
    asm volatile("cp.async.cg.shared.global [%0], [%1], 16;\n"
                 :: "r"(dst), "l"(src));
}
#define CP_COMMIT() asm volatile("cp.async.commit_group;\n")
#define CP_WAIT1()  asm volatile("cp.async.wait_group 1;\n")
#define CP_WAIT0()  asm volatile("cp.async.wait_group 0;\n")

__device__ __forceinline__ float ex2(float x) {
    float r;
    asm("ex2.approx.f32 %0, %1;" : "=f"(r) : "f"(x));
    return r;
}
__device__ __forceinline__ void mma_f16(float d[4], const uint32_t a[4],
                                        const uint32_t b[2], const float c[4]) {
    asm volatile(
        "mma.sync.aligned.m16n8k16.row.col.f32.f16.f16.f32 "
        "{%0,%1,%2,%3}, {%4,%5,%6,%7}, {%8,%9}, {%10,%11,%12,%13};\n"
        : "=f"(d[0]), "=f"(d[1]), "=f"(d[2]), "=f"(d[3])
        : "r"(a[0]), "r"(a[1]), "r"(a[2]), "r"(a[3]),
          "r"(b[0]), "r"(b[1]),
          "f"(c[0]), "f"(c[1]), "f"(c[2]), "f"(c[3]));
}
__device__ __forceinline__ void ldsm4(uint32_t& r0, uint32_t& r1,
                                      uint32_t& r2, uint32_t& r3, uint32_t addr) {
    asm volatile("ldmatrix.sync.aligned.m8n8.x4.shared.b16 {%0,%1,%2,%3}, [%4];\n"
                 : "=r"(r0), "=r"(r1), "=r"(r2), "=r"(r3) : "r"(addr));
}

// ---------------------------------------------------------------------------
// Elementwise fp32 -> fp16 rounding
// ---------------------------------------------------------------------------
__global__ __launch_bounds__(256) void round_f16_kernel(
    const float* __restrict__ in, __half* __restrict__ out, int n4)
{
    int i = blockIdx.x * 256 + threadIdx.x;
    if (i < n4) {
        float4 v = ((const float4*)in)[i];
        __half2 lo = __floats2half2_rn(v.x, v.y);
        __half2 hi = __floats2half2_rn(v.z, v.w);
        uint2 u;
        u.x = *(uint32_t*)&lo; u.y = *(uint32_t*)&hi;
        ((uint2*)out)[i] = u;
    }
}

// ---------------------------------------------------------------------------
// FP16 NT GEMM: C = scale*(A[M,K] @ W[N,K]^T) (+ bias), fp32 accumulate.
// Tile 128x64x64, 128 threads = 4 warps x 32 rows; ldmatrix A and B frags.
// OUT_MODE: 0 = fp32, 2 = half, 3 = half scattered V^T [b][h][d][key]
// ---------------------------------------------------------------------------
#define GSTR 72
#define GEMM_SMEM ((2*128*GSTR + 2*64*GSTR) * 2)

template <bool HAS_BIAS, int OUT_MODE>
__global__ __launch_bounds__(128) void gemm_f16_kernel(
    const __half* __restrict__ A, const __half* __restrict__ W,
    const float* __restrict__ bias, void* __restrict__ Cv,
    int M, int N, int K, float scale)
{
    extern __shared__ __half gsh[];
    __half* sA = gsh;                    // [2][128][72]
    __half* sW = gsh + 2*128*GSTR;       // [2][64][72]
    const uint32_t sA_u = smem_u32(sA);
    const uint32_t sW_u = smem_u32(sW);

    const int tid = threadIdx.x;
    const int lane = tid & 31, w = tid >> 5;
    const int g = lane >> 2, t = lane & 3;
    const int bm = blockIdx.y * 128, bn = blockIdx.x * 64;
    const int NIT = K / 64;

    const int arow = (lane & 15), acol = (lane >> 4)*8;
    const int brow = ((lane >> 4)*8 + (lane & 7));
    const int bcol = ((lane >> 3) & 1)*8;

    float acc[2][8][4];
#pragma unroll
    for (int r = 0; r < 2; r++)
#pragma unroll
        for (int nb = 0; nb < 8; nb++)
#pragma unroll
            for (int j = 0; j < 4; j++) acc[r][nb][j] = 0.f;

    {
#pragma unroll
        for (int i = 0; i < 8; i++) {
            int idx = tid + i*128, row = idx >> 3, c = idx & 7;
            cp16(sA_u + (row*GSTR + c*8)*2, A + (size_t)(bm + row)*K + c*8);
        }
#pragma unroll
        for (int i = 0; i < 4; i++) {
            int idx = tid + i*128, row = idx >> 3, c = idx & 7;
            cp16(sW_u + (row*GSTR + c*8)*2, W + (size_t)(bn + row)*K + c*8);
        }
        CP_COMMIT();
    }

    for (int it = 0; it < NIT; it++) {
        const int buf = it & 1;
        if (it + 1 < NIT) {
            const int k0 = (it + 1) * 64, nbuf = buf ^ 1;
#pragma unroll
            for (int i = 0; i < 8; i++) {
                int idx = tid + i*128, row = idx >> 3, c = idx & 7;
                cp16(sA_u + (nbuf*128*GSTR + row*GSTR + c*8)*2,
                     A + (size_t)(bm + row)*K + k0 + c*8);
            }
#pragma unroll
            for (int i = 0; i < 4; i++) {
                int idx = tid + i*128, row = idx >> 3, c = idx & 7;
                cp16(sW_u + (nbuf*64*GSTR + row*GSTR + c*8)*2,
                     W + (size_t)(bn + row)*K + k0 + c*8);
            }
            CP_COMMIT();
            CP_WAIT1();
        } else {
            CP_WAIT0();
        }
        __syncthreads();

        const uint32_t tA_u = sA_u + buf*128*GSTR*2;
        const uint32_t tW_u = sW_u + buf*64*GSTR*2;

#pragma unroll
        for (int ks = 0; ks < 4; ks++) {
            uint32_t a0[4], a1[4];
            ldsm4(a0[0], a0[1], a0[2], a0[3],
                  tA_u + ((w*32 + arow)*GSTR + ks*16 + acol)*2);
            ldsm4(a1[0], a1[1], a1[2], a1[3],
                  tA_u + ((w*32 + 16 + arow)*GSTR + ks*16 + acol)*2);
#pragma unroll
            for (int p = 0; p < 4; p++) {
                uint32_t b0, b1, b2, b3;
                ldsm4(b0, b1, b2, b3,
                      tW_u + ((p*16 + brow)*GSTR + ks*16 + bcol)*2);
                uint32_t bl[2] = {b0, b1}, bh[2] = {b2, b3};
                mma_f16(acc[0][2*p    ], a0, bl, acc[0][2*p    ]);
                mma_f16(acc[0][2*p + 1], a0, bh, acc[0][2*p + 1]);
                mma_f16(acc[1][2*p    ], a1, bl, acc[1][2*p    ]);
                mma_f16(acc[1][2*p + 1], a1, bh, acc[1][2*p + 1]);
            }
        }
        __syncthreads();
    }

#pragma unroll
    for (int r = 0; r < 2; r++) {
        const int r0 = bm + w*32 + r*16 + g, r1 = r0 + 8;
#pragma unroll
        for (int nb = 0; nb < 8; nb++) {
            const int col = bn + nb*8 + 2*t;
            float v00 = acc[r][nb][0]*scale, v01 = acc[r][nb][1]*scale;
            float v10 = acc[r][nb][2]*scale, v11 = acc[r][nb][3]*scale;
            if (HAS_BIAS) {
                float b0 = bias[col], b1 = bias[col + 1];
                v00 += b0; v01 += b1; v10 += b0; v11 += b1;
            }
            if (OUT_MODE == 0) {
                float* C = (float*)Cv;
                *(float2*)&C[(size_t)r0*N + col] = make_float2(v00, v01);
                *(float2*)&C[(size_t)r1*N + col] = make_float2(v10, v11);
            } else if (OUT_MODE == 2) {
                __half* C = (__half*)Cv;
                *(__half2*)&C[(size_t)r0*N + col] = __floats2half2_rn(v00, v01);
                *(__half2*)&C[(size_t)r1*N + col] = __floats2half2_rn(v10, v11);
            } else {
                __half* C = (__half*)Cv;
                int b_ = r0 >> 12;
                int key0 = r0 & (NKV - 1), key1 = r1 & (NKV - 1);
                size_t base0 = ((size_t)(b_*NH + (col >> 6))*HD + (col & 63)) * NKV;
                size_t base1 = base0 + NKV;
                C[base0 + key0] = __float2half_rn(v00);
                C[base1 + key0] = __float2half_rn(v01);
                C[base0 + key1] = __float2half_rn(v10);
                C[base1 + key1] = __float2half_rn(v11);
            }
        }
    }
}

// ---------------------------------------------------------------------------
// Flash-attention core, fp16 + m16n8k16, fp32 accumulate.
// 4 warps x 32 q-rows, BQ=128, 2 CTAs/SM.
// R12: phase-overlap schedule — PV HMMAs are fire-and-forget (o is only read
// at the NEXT iteration's correction), so issue PV(half A) before ex2(half B):
// MUFU and tensor pipes overlap instead of serializing.  Arithmetic identical
// to R11 (same ops, same order) -> rel_err must be bit-identical.
// ---------------------------------------------------------------------------
#define BQ    128
#define KT    64
#define STRH  72
#define NITA  (NKV / KT)
#define ATTN_SMEM ((2*KT*STRH + 2*KT*STRH + BQ*STRH) * 2)

__global__ __launch_bounds__(128, 2) void attn_mma_kernel()
{
    extern __shared__ __half smh[];
    __half* sK  = smh;                   // [2][64][72]
    __half* sVt = sK + 2*KT*STRH;        // [2][64][72]
    __half* sQP = sVt + 2*KT*STRH;       // [128][72]
    const uint32_t sK_u  = smem_u32(sK);
    const uint32_t sVt_u = smem_u32(sVt);
    const uint32_t sQP_u = smem_u32(sQP);

    const int qt = blockIdx.x, h = blockIdx.y, b = blockIdx.z;
    const int tid = threadIdx.x, lane = tid & 31, w = tid >> 5;
    const int g = lane >> 2, t = lane & 3;

    const __half* Qb  = g_Qh + (size_t)(b*NQ + qt*BQ)*INNER + h*HD;
    const __half* Kb  = g_Kh + (size_t)b*NKV*INNER + h*HD;
    const __half* Vtb = g_Vh + ((size_t)(b*NH + h)*HD)*NKV;

    const int kvrow = ((lane >> 4)*8 + (lane & 7));
    const int kvcol = ((lane >> 3) & 1)*8;
    const int prow = (lane & 15);
    const int pcol = (lane >> 4)*8;

#pragma unroll
    for (int i = 0; i < 8; i++) {
        int idx = tid + i*128, row = idx >> 3, c = idx & 7;
        cp16(sQP_u + (row*STRH + c*8)*2, Qb + (size_t)row*INNER + c*8);
    }
    CP_COMMIT();

#pragma unroll
    for (int i = 0; i < 4; i++) {
        int idx = tid + i*128, row = idx >> 3, c = idx & 7;
        cp16(sK_u  + (row*STRH + c*8)*2, Kb  + (size_t)row*INNER + c*8);
        cp16(sVt_u + (row*STRH + c*8)*2, Vtb + (size_t)row*NKV   + c*8);
    }
    CP_COMMIT();

    CP_WAIT1();
    __syncthreads();

    uint32_t qa[2][4][4];
#pragma unroll
    for (int r = 0; r < 2; r++)
#pragma unroll
        for (int ks = 0; ks < 4; ks++) {
            const int row = w*32 + r*16;
            const int c0 = ks*16 + 2*t;
            qa[r][ks][0] = *(const uint32_t*)&sQP[(row + g    )*STRH + c0];
            qa[r][ks][1] = *(const uint32_t*)&sQP[(row + g + 8)*STRH + c0];
            qa[r][ks][2] = *(const uint32_t*)&sQP[(row + g    )*STRH + c0 + 8];
            qa[r][ks][3] = *(const uint32_t*)&sQP[(row + g + 8)*STRH + c0 + 8];
        }

    float m0[2], m1[2], l0[2], l1[2];
#pragma unroll
    for (int r = 0; r < 2; r++) { m0[r] = m1[r] = -INFINITY; l0[r] = l1[r] = 0.f; }
    float o[2][8][4];
#pragma unroll
    for (int r = 0; r < 2; r++)
#pragma unroll
        for (int db = 0; db < 8; db++)
#pragma unroll
            for (int j = 0; j < 4; j++) o[r][db][j] = 0.f;

    __half* sPw = sQP + (w*32)*STRH;
    const uint32_t sPw_u = sQP_u + (w*32)*STRH*2;

    for (int it = 0; it < NITA; it++) {
        const int buf = it & 1;
        if (it + 1 < NITA) {
            const int nbuf = buf ^ 1;
#pragma unroll
            for (int i = 0; i < 4; i++) {
                int idx = tid + i*128, row = idx >> 3, c = idx & 7;
                cp16(sK_u  + (nbuf*KT*STRH + row*STRH + c*8)*2,
                     Kb  + (size_t)((it + 1)*KT + row)*INNER + c*8);
                cp16(sVt_u + (nbuf*KT*STRH + row*STRH + c*8)*2,
                     Vtb + (size_t)row*NKV + (it + 1)*KT + c*8);
            }
            CP_COMMIT();
            CP_WAIT1();
        } else {
            CP_WAIT0();
        }
        __syncthreads();

        const uint32_t tK_u  = sK_u  + buf*KT*STRH*2;
        const uint32_t tVt_u = sVt_u + buf*KT*STRH*2;

        // ---- S = Q K^T ----
        float s[2][8][4];
#pragma unroll
        for (int r = 0; r < 2; r++)
#pragma unroll
            for (int nb = 0; nb < 8; nb++)
#pragma unroll
                for (int j = 0; j < 4; j++) s[r][nb][j] = 0.f;

#pragma unroll
        for (int ks = 0; ks < 4; ks++) {
#pragma unroll
            for (int p = 0; p < 4; p++) {
                uint32_t b0, b1, b2, b3;
                ldsm4(b0, b1, b2, b3,
                      tK_u + ((p*16 + kvrow)*STRH + ks*16 + kvcol)*2);
                uint32_t bl[2] = {b0, b1}, bh[2] = {b2, b3};
                mma_f16(s[0][2*p    ], qa[0][ks], bl, s[0][2*p    ]);
                mma_f16(s[0][2*p + 1], qa[0][ks], bh, s[0][2*p + 1]);
                mma_f16(s[1][2*p    ], qa[1][ks], bl, s[1][2*p    ]);
                mma_f16(s[1][2*p + 1], qa[1][ks], bh, s[1][2*p + 1]);
            }
        }

        // ---- full-tile max, correction, o-scale (both row-blocks) ----
        float corr0[2], corr1[2], rs0[2], rs1[2];
#pragma unroll
        for (int r = 0; r < 2; r++) {
            float rm0 = -INFINITY, rm1 = -INFINITY;
#pragma unroll
            for (int nb = 0; nb < 8; nb++) {
                rm0 = fmaxf(rm0, fmaxf(s[r][nb][0], s[r][nb][1]));
                rm1 = fmaxf(rm1, fmaxf(s[r][nb][2], s[r][nb][3]));
            }
            rm0 = fmaxf(rm0, __shfl_xor_sync(0xffffffffu, rm0, 1));
            rm0 = fmaxf(rm0, __shfl_xor_sync(0xffffffffu, rm0, 2));
            rm1 = fmaxf(rm1, __shfl_xor_sync(0xffffffffu, rm1, 1));
            rm1 = fmaxf(rm1, __shfl_xor_sync(0xffffffffu, rm1, 2));

            float mn0 = fmaxf(m0[r], rm0), mn1 = fmaxf(m1[r], rm1);
            corr0[r] = ex2(m0[r] - mn0); corr1[r] = ex2(m1[r] - mn1);
            m0[r] = mn0; m1[r] = mn1;
            rs0[r] = 0.f; rs1[r] = 0.f;

#pragma unroll
            for (int db = 0; db < 8; db++) {
                o[r][db][0] *= corr0[r]; o[r][db][1] *= corr0[r];
                o[r][db][2] *= corr1[r]; o[r][db][3] *= corr1[r];
            }
        }

        // ---- half A: ex2 + P store for keys 0..31 (nb 0..3) ----
#pragma unroll
        for (int r = 0; r < 2; r++) {
#pragma unroll
            for (int nb = 0; nb < 4; nb++) {
                s[r][nb][0] = ex2(s[r][nb][0] - m0[r]);
                s[r][nb][1] = ex2(s[r][nb][1] - m0[r]);
                s[r][nb][2] = ex2(s[r][nb][2] - m1[r]);
                s[r][nb][3] = ex2(s[r][nb][3] - m1[r]);
                rs0[r] += s[r][nb][0] + s[r][nb][1];
                rs1[r] += s[r][nb][2] + s[r][nb][3];
                *(__half2*)&sPw[(r*16 + g    )*STRH + nb*8 + 2*t] =
                    __floats2half2_rn(s[r][nb][0], s[r][nb][1]);
                *(__half2*)&sPw[(r*16 + g + 8)*STRH + nb*8 + 2*t] =
                    __floats2half2_rn(s[r][nb][2], s[r][nb][3]);
            }
        }
        __syncwarp();

        // ---- PV for keys 0..31 (ks 0..1): fire-and-forget into o ----
#pragma unroll
        for (int ks = 0; ks < 2; ks++) {
            uint32_t pa0[4], pa1[4];
            ldsm4(pa0[0], pa0[1], pa0[2], pa0[3],
                  sPw_u + ((prow     )*STRH + ks*16 + pcol)*2);
            ldsm4(pa1[0], pa1[1], pa1[2], pa1[3],
                  sPw_u + ((prow + 16)*STRH + ks*16 + pcol)*2);
#pragma unroll
            for (int p = 0; p < 4; p++) {
                uint32_t b0, b1, b2, b3;
                ldsm4(b0, b1, b2, b3,
                      tVt_u + ((p*16 + kvrow)*STRH + ks*16 + kvcol)*2);
                uint32_t bl[2] = {b0, b1}, bh[2] = {b2, b3};
                mma_f16(o[0][2*p    ], pa0, bl, o[0][2*p    ]);
                mma_f16(o[0][2*p + 1], pa0, bh, o[0][2*p + 1]);
                mma_f16(o[1][2*p    ], pa1, bl, o[1][2*p    ]);
                mma_f16(o[1][2*p + 1], pa1, bh, o[1][2*p + 1]);
            }
        }

        // ---- half B: ex2 + P store for keys 32..63 (nb 4..7) ----
        // MUFU work here overlaps the PV(A) HMMAs still in the tensor pipe.
#pragma unroll
        for (int r = 0; r < 2; r++) {
#pragma unroll
            for (int nb = 4; nb < 8; nb++) {
                s[r][nb][0] = ex2(s[r][nb][0] - m0[r]);
                s[r][nb][1] = ex2(s[r][nb][1] - m0[r]);
                s[r][nb][2] = ex2(s[r][nb][2] - m1[r]);
                s[r][nb][3] = ex2(s[r][nb][3] - m1[r]);
                rs0[r] += s[r][nb][0] + s[r][nb][1];
                rs1[r] += s[r][nb][2] + s[r][nb][3];
                *(__half2*)&sPw[(r*16 + g    )*STRH + nb*8 + 2*t] =
                    __floats2half2_rn(s[r][nb][0], s[r][nb][1]);
                *(__half2*)&sPw[(r*16 + g + 8)*STRH + nb*8 + 2*t] =
                    __floats2half2_rn(s[r][nb][2], s[r][nb][3]);
            }
        }
        __syncwarp();

        // ---- PV for keys 32..63 (ks 2..3) ----
#pragma unroll
        for (int ks = 2; ks < 4; ks++) {
            uint32_t pa0[4], pa1[4];
            ldsm4(pa0[0], pa0[1], pa0[2], pa0[3],
                  sPw_u + ((prow     )*STRH + ks*16 + pcol)*2);
            ldsm4(pa1[0], pa1[1], pa1[2], pa1[3],
                  sPw_u + ((prow + 16)*STRH + ks*16 + pcol)*2);
#pragma unroll
            for (int p = 0; p < 4; p++) {
                uint32_t b0, b1, b2, b3;
                ldsm4(b0, b1, b2, b3,
                      tVt_u + ((p*16 + kvrow)*STRH + ks*16 + kvcol)*2);
                uint32_t bl[2] = {b0, b1}, bh[2] = {b2, b3};
                mma_f16(o[0][2*p    ], pa0, bl, o[0][2*p    ]);
                mma_f16(o[0][2*p + 1], pa0, bh, o[0][2*p + 1]);
                mma_f16(o[1][2*p    ], pa1, bl, o[1][2*p    ]);
                mma_f16(o[1][2*p + 1], pa1, bh, o[1][2*p + 1]);
            }
        }

        // ---- l update (same reduce order/values as R11) ----
#pragma unroll
        for (int r = 0; r < 2; r++) {
            rs0[r] += __shfl_xor_sync(0xffffffffu, rs0[r], 1);
            rs0[r] += __shfl_xor_sync(0xffffffffu, rs0[r], 2);
            rs1[r] += __shfl_xor_sync(0xffffffffu, rs1[r], 1);
            rs1[r] += __shfl_xor_sync(0xffffffffu, rs1[r], 2);
            l0[r] = l0[r] * corr0[r] + rs0[r];
            l1[r] = l1[r] * corr1[r] + rs1[r];
        }
        __syncthreads();
    }

    // ---- epilogue ----
#pragma unroll
    for (int r = 0; r < 2; r++) {
        const float inv0 = 1.f / l0[r], inv1 = 1.f / l1[r];
        const int q0 = qt*BQ + w*32 + r*16 + g, q1 = q0 + 8;
#pragma unroll
        for (int db = 0; db < 8; db++) {
            *(__half2*)&g_AOh[(size_t)(b*NQ + q0)*INNER + h*HD + db*8 + 2*t] =
                __floats2half2_rn(o[r][db][0]*inv0, o[r][db][1]*inv0);
            *(__half2*)&g_AOh[(size_t)(b*NQ + q1)*INNER + h*HD + db*8 + 2*t] =
                __floats2half2_rn(o[r][db][2]*inv1, o[r][db][3]*inv1);
        }
    }
}

// ---------------------------------------------------------------------------
// Launch
// ---------------------------------------------------------------------------
extern "C" void kernel_launch(void* const* d_in, const int* in_sizes, int n_in,
                              void* d_out, int out_size)
{
    const float* q   = (const float*)d_in[0];
    const float* kv  = (const float*)d_in[1];
    const float* w_q = (const float*)d_in[2];
    const float* w_k = (const float*)d_in[3];
    const float* w_v = (const float*)d_in[4];
    const float* w_o = (const float*)d_in[5];
    const float* b_o = (const float*)d_in[6];
    float* out = (float*)d_out;

    void *Qh, *Kh, *Vh, *AOh, *Rq, *Rkv, *Rwq, *Rwk, *Rwv, *Rwo;
    cudaGetSymbolAddress(&Qh,  g_Qh);
    cudaGetSymbolAddress(&Kh,  g_Kh);
    cudaGetSymbolAddress(&Vh,  g_Vh);
    cudaGetSymbolAddress(&AOh, g_AOh);
    cudaGetSymbolAddress(&Rq,  g_Rq);
    cudaGetSymbolAddress(&Rkv, g_Rkv);
    cudaGetSymbolAddress(&Rwq, g_Rwq);
    cudaGetSymbolAddress(&Rwk, g_Rwk);
    cudaGetSymbolAddress(&Rwv, g_Rwv);
    cudaGetSymbolAddress(&Rwo, g_Rwo);

    const int MQ = BB * NQ;    // 8192
    const int MK = BB * NKV;   // 16384

    cudaFuncSetAttribute(gemm_f16_kernel<false, 2>,
                         cudaFuncAttributeMaxDynamicSharedMemorySize, GEMM_SMEM);
    cudaFuncSetAttribute(gemm_f16_kernel<false, 3>,
                         cudaFuncAttributeMaxDynamicSharedMemorySize, GEMM_SMEM);
    cudaFuncSetAttribute(gemm_f16_kernel<true, 0>,
                         cudaFuncAttributeMaxDynamicSharedMemorySize, GEMM_SMEM);
    cudaFuncSetAttribute(attn_mma_kernel,
                         cudaFuncAttributeMaxDynamicSharedMemorySize, ATTN_SMEM);

    // ---- pre-round GEMM inputs to fp16 ----
    {
        int n;
        n = MQ*QDIM/4;      round_f16_kernel<<<(n+255)/256, 256>>>(q,   (__half*)Rq,  n);
        n = MK*KVDIM/4;     round_f16_kernel<<<(n+255)/256, 256>>>(kv,  (__half*)Rkv, n);
        n = INNER*QDIM/4;   round_f16_kernel<<<(n+255)/256, 256>>>(w_q, (__half*)Rwq, n);
        n = INNER*KVDIM/4;  round_f16_kernel<<<(n+255)/256, 256>>>(w_k, (__half*)Rwk, n);
        n = INNER*KVDIM/4;  round_f16_kernel<<<(n+255)/256, 256>>>(w_v, (__half*)Rwv, n);
        n = QDIM*INNER/4;   round_f16_kernel<<<(n+255)/256, 256>>>(w_o, (__half*)Rwo, n);
    }

    gemm_f16_kernel<false, 2><<<dim3(INNER/64, MQ/128), 128, GEMM_SMEM>>>(
        (__half*)Rq, (__half*)Rwq, nullptr, Qh, MQ, INNER, QDIM, Q_PRESCALE);
    gemm_f16_kernel<false, 2><<<dim3(INNER/64, MK/128), 128, GEMM_SMEM>>>(
        (__half*)Rkv, (__half*)Rwk, nullptr, Kh, MK, INNER, KVDIM, 1.0f);
    gemm_f16_kernel<false, 3><<<dim3(INNER/64, MK/128), 128, GEMM_SMEM>>>(
        (__half*)Rkv, (__half*)Rwv, nullptr, Vh, MK, INNER, KVDIM, 1.0f);

    attn_mma_kernel<<<dim3(NQ/BQ, NH, BB), 128, ATTN_SMEM>>>();

    gemm_f16_kernel<true, 0><<<dim3(QDIM/64, MQ/128), 128, GEMM_SMEM>>>(
        (__half*)AOh, (__half*)Rwo, b_o, out, MQ, QDIM, INNER, 1.0f);
}